// round 7
// baseline (speedup 1.0000x reference)
#include <cuda_runtime.h>
#include <cstdint>

#define NP 200000
#define NO 100000
#define NL 50000
#define NE 1000000
#define HD 64

#define GP 50000   // person groups (4 nodes each)
#define GO 25000
#define GL 12500
#define NCNT (3 * NP + NO + NL)   // 750000

// ---------------- device scratch (static, allowed) ----------------
__device__ float g_nodes[2][(size_t)(NP + NO + NL) * HD];   // double-buffered features
__device__ int   g_csr[5 * NE];                             // single global CSR
__device__ int   g_rowoff[NCNT + 8];                        // global exclusive scan
__device__ int   g_cnt[NCNT];                               // counts, then cursors
__device__ int   g_part[256];                               // scan partials
__device__ float g_sums[3 * HD];                            // column sums

// ---------------- utility kernels ----------------
__global__ void zero_kernel(float* __restrict__ p, size_t n) {
    size_t n4 = n >> 2;
    float4 z = make_float4(0.f, 0.f, 0.f, 0.f);
    for (size_t i = (size_t)blockIdx.x * blockDim.x + threadIdx.x; i < n4;
         i += (size_t)gridDim.x * blockDim.x)
        reinterpret_cast<float4*>(p)[i] = z;
}

__global__ void gather_all(const int* __restrict__ xp, const int* __restrict__ xo,
                           const int* __restrict__ xl,
                           const float* __restrict__ pe, const float* __restrict__ oe,
                           const float* __restrict__ le, float* __restrict__ out) {
    int i = blockIdx.x * blockDim.x + threadIdx.x;
    int total = (NP + NO + NL) * 16;
    if (i >= total) return;
    int node = i >> 4, c = i & 15;
    const int* idx;
    const float* emb;
    int local;
    if (node < NP) { idx = xp; emb = pe; local = node; }
    else if (node < NP + NO) { idx = xo; emb = oe; local = node - NP; }
    else { idx = xl; emb = le; local = node - NP - NO; }
    int e = __ldg(&idx[local]);
    reinterpret_cast<float4*>(out)[(size_t)node * 16 + c] =
        reinterpret_cast<const float4*>(emb)[(size_t)e * 16 + c];
}

// ---------------- CSR build: one pass over all 5 relations ----------------
__global__ void count_all(const int* __restrict__ acts_dst, const int* __restrict__ uses_src,
                          const int* __restrict__ at_src, const int* __restrict__ uses_dst,
                          const int* __restrict__ at_dst, int* __restrict__ cnt) {
    int i = blockIdx.x * blockDim.x + threadIdx.x;
    if (i >= 5 * NE) return;
    int rel = i / NE, e = i - rel * NE;
    int d, off;
    switch (rel) {
        case 0: d = __ldg(&acts_dst[e]); off = 0;           break;
        case 1: d = __ldg(&uses_src[e]); off = NP;          break;
        case 2: d = __ldg(&at_src[e]);   off = 2 * NP;      break;
        case 3: d = __ldg(&uses_dst[e]); off = 3 * NP;      break;
        default: d = __ldg(&at_dst[e]);  off = 3 * NP + NO; break;
    }
    atomicAdd(&cnt[off + d], 1);
}

#define SCHUNK 4096
__global__ void scan_reduce(const int* __restrict__ in, int* __restrict__ part, int n) {
    __shared__ int s[256];
    int base = blockIdx.x * SCHUNK;
    int acc = 0;
    for (int i = threadIdx.x; i < SCHUNK; i += 256) {
        int idx = base + i;
        if (idx < n) acc += in[idx];
    }
    s[threadIdx.x] = acc;
    __syncthreads();
    for (int off = 128; off; off >>= 1) {
        if (threadIdx.x < off) s[threadIdx.x] += s[threadIdx.x + off];
        __syncthreads();
    }
    if (threadIdx.x == 0) part[blockIdx.x] = s[0];
}

// block-parallel exclusive scan of <=256 partials
__global__ void scan_part(int* part, int nb) {
    int tid = threadIdx.x;
    int v = tid < nb ? part[tid] : 0;
    int lane = tid & 31, wp = tid >> 5;
    int x = v;
#pragma unroll
    for (int off = 1; off < 32; off <<= 1) {
        int y = __shfl_up_sync(0xffffffffu, x, off);
        if (lane >= off) x += y;
    }
    __shared__ int ws[8];
    if (lane == 31) ws[wp] = x;
    __syncthreads();
    if (tid == 0) {
        int run = 0;
        for (int i = 0; i < 8; i++) { int t = ws[i]; ws[i] = run; run += t; }
    }
    __syncthreads();
    int incl = x + ws[wp];
    if (tid < nb) part[tid] = incl - v;
    if (tid == nb - 1) part[nb] = incl;
}

__global__ void scan_write(const int* __restrict__ in, const int* __restrict__ part,
                           int* __restrict__ ro, int n, int nb) {
    __shared__ int wsum[8];
    int base = blockIdx.x * SCHUNK;
    int vals[16];
    int tsum = 0;
    int tb = base + threadIdx.x * 16;
#pragma unroll
    for (int j = 0; j < 16; j++) {
        int idx = tb + j;
        int v = (idx < n) ? in[idx] : 0;
        vals[j] = tsum;
        tsum += v;
    }
    int lane = threadIdx.x & 31, wp = threadIdx.x >> 5;
    int xs = tsum;
#pragma unroll
    for (int off = 1; off < 32; off <<= 1) {
        int y = __shfl_up_sync(0xffffffffu, xs, off);
        if (lane >= off) xs += y;
    }
    if (lane == 31) wsum[wp] = xs;
    int wex = xs - tsum;
    __syncthreads();
    if (threadIdx.x == 0) {
        int run = 0;
        for (int i = 0; i < 8; i++) { int v = wsum[i]; wsum[i] = run; run += v; }
    }
    __syncthreads();
    int off0 = part[blockIdx.x] + wsum[wp] + wex;
#pragma unroll
    for (int j = 0; j < 16; j++) {
        int idx = tb + j;
        if (idx < n) ro[idx] = off0 + vals[j];
    }
    if (blockIdx.x == 0 && threadIdx.x == 0) ro[n] = part[nb];
}

__global__ void copy_int(const int* __restrict__ src, int* __restrict__ dst, int n4) {
    int i = blockIdx.x * blockDim.x + threadIdx.x;
    if (i < n4) reinterpret_cast<int4*>(dst)[i] = reinterpret_cast<const int4*>(src)[i];
}

__global__ void fill_all(const int* __restrict__ acts_src, const int* __restrict__ acts_dst,
                         const int* __restrict__ uses_src, const int* __restrict__ uses_dst,
                         const int* __restrict__ at_src, const int* __restrict__ at_dst,
                         int* __restrict__ cur, int* __restrict__ csr) {
    int i = blockIdx.x * blockDim.x + threadIdx.x;
    if (i >= 5 * NE) return;
    int rel = i / NE, e = i - rel * NE;
    int d, s, off;
    switch (rel) {
        case 0: d = __ldg(&acts_dst[e]); s = __ldg(&acts_src[e]); off = 0;           break;
        case 1: d = __ldg(&uses_src[e]); s = __ldg(&uses_dst[e]); off = NP;          break;
        case 2: d = __ldg(&at_src[e]);   s = __ldg(&at_dst[e]);   off = 2 * NP;      break;
        case 3: d = __ldg(&uses_dst[e]); s = __ldg(&uses_src[e]); off = 3 * NP;      break;
        default: d = __ldg(&at_dst[e]);  s = __ldg(&at_src[e]);   off = 3 * NP + NO; break;
    }
    int pos = atomicAdd(&cur[off + d], 1);
    csr[pos] = s;
}

// ---------------- packed f32x2 FMA (no dup-mov: e comes pre-duplicated) ----------------
__device__ __forceinline__ void fma2p(unsigned long long& acc, unsigned long long w,
                                      unsigned long long e) {
    asm("fma.rn.f32x2 %0, %1, %2, %0;" : "+l"(acc) : "l"(w), "l"(e));
}

// ---------------- unified fused aggregate + SAGE combine ----------------
#define WSTRIDE 66                    // padded row stride (floats) -> no STS bank conflicts
#define WMAT (64 * WSTRIDE)           // 4224 floats per matrix
#define NWARP 11                      // warps per block (smem budget)
#define STSLOT 128                    // duplicated stage row: 64 values x2
#define STWARP (16 * STSLOT)          // 4 nodes * 4 slots * 128 floats

template <int NR, int MA, int MB, int MC, int MD>
__device__ __forceinline__ void do_group(
    int nd0, int n, const float* __restrict__ x, float* __restrict__ out,
    const float* s0, const float* s1, const float* s2,
    const int* ro0, const int* ro1, const int* ro2,
    const int* __restrict__ csr,
    const float* __restrict__ WT, const float* __restrict__ bias,
    float* __restrict__ st, int lane, float inv) {
    constexpr int mats[4] = {MA, MB, MC, MD};
    const float* srcs[3] = {s0, s1, s2};
    const int* ros[3] = {ro0, ro1, ro2};
    float2 xv[4];
#pragma unroll
    for (int m = 0; m < 4; m++) {
        int nd = nd0 + m;
        bool act = nd < n;
        int ndc = act ? nd : 0;
#pragma unroll
        for (int r = 0; r < NR; r++) {
            int base = __ldg(&ros[r][ndc]);
            int deg = act ? (__ldg(&ros[r][ndc + 1]) - base) : 0;
            const float* S = srcs[r];
            const int* C = csr + base;
            float sx = 0.f, sy = 0.f;
            int i = 0;
            for (; i + 4 <= deg; i += 4) {
                int n0 = __ldg(C + i), n1 = __ldg(C + i + 1);
                int n2 = __ldg(C + i + 2), n3 = __ldg(C + i + 3);
                float2 v0 = *reinterpret_cast<const float2*>(S + (size_t)n0 * HD + 2 * lane);
                float2 v1 = *reinterpret_cast<const float2*>(S + (size_t)n1 * HD + 2 * lane);
                float2 v2 = *reinterpret_cast<const float2*>(S + (size_t)n2 * HD + 2 * lane);
                float2 v3 = *reinterpret_cast<const float2*>(S + (size_t)n3 * HD + 2 * lane);
                sx += (v0.x + v1.x) + (v2.x + v3.x);
                sy += (v0.y + v1.y) + (v2.y + v3.y);
            }
            for (; i < deg; i++) {
                int nn = __ldg(C + i);
                float2 v = *reinterpret_cast<const float2*>(S + (size_t)nn * HD + 2 * lane);
                sx += v.x; sy += v.y;
            }
            float ic = deg > 0 ? 1.0f / (float)deg : 0.f;
            // duplicated stage: {v,v,w,w} as one STS.128
            float4 dup = make_float4(sx * ic, sx * ic, sy * ic, sy * ic);
            *reinterpret_cast<float4*>(st + (m * (NR + 1) + r) * STSLOT + 4 * lane) = dup;
        }
        float2 xx = *reinterpret_cast<const float2*>(x + (size_t)ndc * HD + 2 * lane);
        xv[m] = xx;
        float4 dup = make_float4(xx.x, xx.x, xx.y, xx.y);
        *reinterpret_cast<float4*>(st + (m * (NR + 1) + NR) * STSLOT + 4 * lane) = dup;
    }
    __syncwarp();

    float2 bb = *reinterpret_cast<const float2*>(bias + 2 * lane);
    unsigned long long accb;
    asm("mov.b64 %0, {%1, %2};" : "=l"(accb) : "f"(bb.x), "f"(bb.y));
    unsigned long long acc0 = accb, acc1 = accb, acc2 = accb, acc3 = accb;
#pragma unroll 8
    for (int k0 = 0; k0 < 64; k0 += 2) {
#pragma unroll
        for (int mi = 0; mi < NR + 1; mi++) {
            const float* Wm = WT + mats[mi] * WMAT;
            unsigned long long w0 = *reinterpret_cast<const unsigned long long*>(
                Wm + k0 * WSTRIDE + 2 * lane);
            unsigned long long w1 = *reinterpret_cast<const unsigned long long*>(
                Wm + (k0 + 1) * WSTRIDE + 2 * lane);
            const float* sb = st + mi * STSLOT + 2 * k0;
            ulonglong2 e0 = *reinterpret_cast<const ulonglong2*>(sb + 0 * (NR + 1) * STSLOT);
            ulonglong2 e1 = *reinterpret_cast<const ulonglong2*>(sb + 1 * (NR + 1) * STSLOT);
            ulonglong2 e2 = *reinterpret_cast<const ulonglong2*>(sb + 2 * (NR + 1) * STSLOT);
            ulonglong2 e3 = *reinterpret_cast<const ulonglong2*>(sb + 3 * (NR + 1) * STSLOT);
            fma2p(acc0, w0, e0.x); fma2p(acc0, w1, e0.y);
            fma2p(acc1, w0, e1.x); fma2p(acc1, w1, e1.y);
            fma2p(acc2, w0, e2.x); fma2p(acc2, w1, e2.y);
            fma2p(acc3, w0, e3.x); fma2p(acc3, w1, e3.y);
        }
    }
#pragma unroll
    for (int m = 0; m < 4; m++) {
        int nd = nd0 + m;
        if (nd >= n) break;
        unsigned long long a = m == 0 ? acc0 : m == 1 ? acc1 : m == 2 ? acc2 : acc3;
        float ax, ay;
        asm("mov.b64 {%0, %1}, %2;" : "=f"(ax), "=f"(ay) : "l"(a));
        float2 res;
        res.x = fmaxf(ax * inv, 0.f) + xv[m].x;
        res.y = fmaxf(ay * inv, 0.f) + xv[m].y;
        *reinterpret_cast<float2*>(out + (size_t)nd * HD + 2 * lane) = res;
    }
    __syncwarp();
}

// smem: 8 mats * WMAT + 192 bias + NWARP * STWARP stage  (= 226048 B)
#define SMEMC ((8 * WMAT + 192 + NWARP * STWARP) * 4)

__global__ void __launch_bounds__(NWARP * 32, 1) combine_all(
    const float* __restrict__ xin, float* __restrict__ xout,
    const int* __restrict__ rowoff, const int* __restrict__ csr,
    const float* __restrict__ Wl, const float* __restrict__ blv,
    const float* __restrict__ Wr, int t) {
    extern __shared__ float sm[];
    float* WT   = sm;                   // 8 mats, stride-padded, transposed [k][c]
    float* bias = WT + 8 * WMAT;        // 3 * 64
    float* stage = bias + 192;          // NWARP * STWARP (duplicated pairs)

    const int tid = threadIdx.x;
    const int nthr = NWARP * 32;
    const float* WlB = Wl + (size_t)t * 5 * 4096;
    const float* WrB = Wr + (size_t)t * 5 * 4096;
    // mats 0..4 = Wl[t][0..4]^T
    for (int i = tid; i < 5 * 4096; i += nthr) {
        int m = i >> 12, j = i & 4095;
        int c = j >> 6, k = j & 63;
        WT[m * WMAT + k * WSTRIDE + c] = WlB[i];
    }
    // mat 5 = (Wr0+Wr2+Wr4)^T, mat 6 = Wr1^T, mat 7 = Wr3^T
    for (int i = tid; i < 4096; i += nthr) {
        int c = i >> 6, k = i & 63;
        WT[5 * WMAT + k * WSTRIDE + c] = WrB[i] + WrB[2 * 4096 + i] + WrB[4 * 4096 + i];
        WT[6 * WMAT + k * WSTRIDE + c] = WrB[4096 + i];
        WT[7 * WMAT + k * WSTRIDE + c] = WrB[3 * 4096 + i];
    }
    if (tid < 64) {
        const float* b = blv + (size_t)t * 5 * 64;
        bias[tid]       = b[tid] + b[128 + tid] + b[256 + tid];
        bias[64 + tid]  = b[64 + tid];
        bias[128 + tid] = b[192 + tid];
    }
    __syncthreads();

    const int lane = tid & 31, w = tid >> 5;
    float* st = stage + w * STWARP;
    const float* P  = xin;
    const float* O  = xin + (size_t)NP * HD;
    const float* Lc = xin + (size_t)(NP + NO) * HD;

    for (int g = blockIdx.x * NWARP + w; g < GP + GO + GL; g += gridDim.x * NWARP) {
        if (g < GP) {
            do_group<3, 0, 2, 4, 5>(g * 4, NP, P, xout,
                P, O, Lc, rowoff, rowoff + NP, rowoff + 2 * NP, csr,
                WT, bias, st, lane, 1.0f / 3.0f);
        } else if (g < GP + GO) {
            do_group<1, 1, 6, 0, 0>((g - GP) * 4, NO, O, xout + (size_t)NP * HD,
                P, P, P, rowoff + 3 * NP, rowoff + 3 * NP, rowoff + 3 * NP, csr,
                WT, bias + 64, st, lane, 1.0f);
        } else {
            do_group<1, 3, 7, 0, 0>((g - GP - GO) * 4, NL, Lc, xout + (size_t)(NP + NO) * HD,
                P, P, P, rowoff + 3 * NP + NO, rowoff + 3 * NP + NO, rowoff + 3 * NP + NO, csr,
                WT, bias + 128, st, lane, 1.0f);
        }
    }
}

// ---------------- column sums over all node types in one pass ----------------
__global__ void colsum_all(const float* __restrict__ x, float* __restrict__ sums) {
    const int lane = threadIdx.x & 31;
    const int w = (blockIdx.x * blockDim.x + threadIdx.x) >> 5;
    const int nw = (gridDim.x * blockDim.x) >> 5;
    float2 a0 = make_float2(0.f, 0.f), a1 = a0, a2 = a0;
    for (int r = w; r < NP + NO + NL; r += nw) {
        float2 v = *reinterpret_cast<const float2*>(x + (size_t)r * HD + 2 * lane);
        if (r < NP)          { a0.x += v.x; a0.y += v.y; }
        else if (r < NP + NO){ a1.x += v.x; a1.y += v.y; }
        else                 { a2.x += v.x; a2.y += v.y; }
    }
    asm volatile("red.global.add.v2.f32 [%0], {%1, %2};"
                 :: "l"(sums + 2 * lane), "f"(a0.x), "f"(a0.y) : "memory");
    asm volatile("red.global.add.v2.f32 [%0], {%1, %2};"
                 :: "l"(sums + 64 + 2 * lane), "f"(a1.x), "f"(a1.y) : "memory");
    asm volatile("red.global.add.v2.f32 [%0], {%1, %2};"
                 :: "l"(sums + 128 + 2 * lane), "f"(a2.x), "f"(a2.y) : "memory");
}

// ---------------- crime head (tiny) ----------------
__global__ void head_kernel(const float* __restrict__ gsum,
                            const float* __restrict__ Wc1, const float* __restrict__ bc1,
                            const float* __restrict__ Wc2, const float* __restrict__ bc2,
                            float* __restrict__ out) {
    __shared__ float g[192];
    __shared__ float h[64];
    int tid = threadIdx.x;
    if (tid < 192) {
        float nrm = tid < 64 ? (1.f / NP) : (tid < 128 ? (1.f / NO) : (1.f / NL));
        g[tid] = gsum[tid] * nrm;
    }
    __syncthreads();
    if (tid < 64) {
        float a = bc1[tid];
        for (int k = 0; k < 192; k++) a = fmaf(g[k], Wc1[tid * 192 + k], a);
        h[tid] = fmaxf(a, 0.f);
    }
    __syncthreads();
    if (tid < 20) {
        float a = bc2[tid];
        for (int k = 0; k < 64; k++) a = fmaf(h[k], Wc2[tid * 64 + k], a);
        out[tid] = a;
    }
}

// ---------------- suspect head: per-person MLP 64->32->1 ----------------
__global__ void __launch_bounds__(256) suspect_kernel(
    const float* __restrict__ p, const float* __restrict__ Ws1, const float* __restrict__ bs1,
    const float* __restrict__ Ws2, const float* __restrict__ bs2, float* __restrict__ out) {
    __shared__ float W1T[64 * 32];
    __shared__ float w2[32], b1[32];
    __shared__ float stage[8][64];
    int tid = threadIdx.x;
    for (int i = tid; i < 2048; i += 256) {
        int j = i >> 6, k = i & 63;
        W1T[k * 32 + j] = Ws1[i];
    }
    if (tid < 32) { w2[tid] = Ws2[tid]; b1[tid] = bs1[tid]; }
    __syncthreads();
    const float b2 = __ldg(bs2);
    const int lane = tid & 31, w = tid >> 5;
    const int wg = blockIdx.x * 8 + w;
    const int nw = gridDim.x * 8;
    for (int nd = wg; nd < NP; nd += nw) {
        float2 v = *reinterpret_cast<const float2*>(p + (size_t)nd * HD + 2 * lane);
        stage[w][2 * lane] = v.x; stage[w][2 * lane + 1] = v.y;
        __syncwarp();
        float acc = b1[lane];
#pragma unroll 8
        for (int k = 0; k < 64; k++)
            acc = fmaf(stage[w][k], W1T[k * 32 + lane], acc);
        float s = fmaxf(acc, 0.f) * w2[lane];
#pragma unroll
        for (int off = 16; off; off >>= 1) s += __shfl_xor_sync(0xffffffffu, s, off);
        if (lane == 0) out[20 + nd] = s + b2;
        __syncwarp();
    }
}

// ---------------- orchestration ----------------
extern "C" void kernel_launch(void* const* d_in, const int* in_sizes, int n_in,
                              void* d_out, int out_size) {
    const int* x_person   = (const int*)d_in[0];
    const int* x_object   = (const int*)d_in[1];
    const int* x_location = (const int*)d_in[2];
    const int* acts_src = (const int*)d_in[3];
    const int* acts_dst = (const int*)d_in[4];
    const int* uses_src = (const int*)d_in[5];
    const int* uses_dst = (const int*)d_in[6];
    const int* at_src   = (const int*)d_in[7];
    const int* at_dst   = (const int*)d_in[8];
    const float* person_emb   = (const float*)d_in[9];
    const float* object_emb   = (const float*)d_in[10];
    const float* location_emb = (const float*)d_in[11];
    const float* Wl  = (const float*)d_in[12];
    const float* bl  = (const float*)d_in[13];
    const float* Wr  = (const float*)d_in[14];
    const float* Wc1 = (const float*)d_in[15];
    const float* bc1 = (const float*)d_in[16];
    const float* Wc2 = (const float*)d_in[17];
    const float* bc2 = (const float*)d_in[18];
    const float* Ws1 = (const float*)d_in[19];
    const float* bs1 = (const float*)d_in[20];
    const float* Ws2 = (const float*)d_in[21];
    const float* bs2 = (const float*)d_in[22];
    float* out = (float*)d_out;

    float* nodes  = nullptr; cudaGetSymbolAddress((void**)&nodes, g_nodes);
    int*   csr    = nullptr; cudaGetSymbolAddress((void**)&csr, g_csr);
    int*   rowoff = nullptr; cudaGetSymbolAddress((void**)&rowoff, g_rowoff);
    int*   cnt    = nullptr; cudaGetSymbolAddress((void**)&cnt, g_cnt);
    int*   part   = nullptr; cudaGetSymbolAddress((void**)&part, g_part);
    float* sums   = nullptr; cudaGetSymbolAddress((void**)&sums, g_sums);

    int nsm = 148;
    cudaDeviceGetAttribute(&nsm, cudaDevAttrMultiProcessorCount, 0);

    const size_t NODESZ = (size_t)(NP + NO + NL) * HD;
    float* bufA = nodes;
    float* bufB = nodes + NODESZ;

    cudaFuncSetAttribute(combine_all, cudaFuncAttributeMaxDynamicSharedMemorySize, SMEMC);

    // Phase A: embedding gathers (all node types, one launch)
    gather_all<<<((NP + NO + NL) * 16 + 255) / 256, 256>>>(
        x_person, x_object, x_location, person_emb, object_emb, location_emb, bufA);

    // Phase B: global CSR build
    zero_kernel<<<256, 256>>>((float*)cnt, (size_t)NCNT);
    count_all<<<(5 * NE + 255) / 256, 256>>>(acts_dst, uses_src, at_src, uses_dst, at_dst, cnt);
    const int NB = (NCNT + SCHUNK - 1) / SCHUNK;   // 184
    scan_reduce<<<NB, 256>>>(cnt, part, NCNT);
    scan_part<<<1, 256>>>(part, NB);
    scan_write<<<NB, 256>>>(cnt, part, rowoff, NCNT, NB);
    copy_int<<<(NCNT / 4 + 255) / 256, 256>>>(rowoff, cnt, NCNT / 4);   // cursors = rowoff
    fill_all<<<(5 * NE + 255) / 256, 256>>>(acts_src, acts_dst, uses_src, uses_dst,
                                            at_src, at_dst, cnt, csr);

    // Phase C: 3 GNN layers, one unified persistent launch per layer
    float* pc = bufA;
    float* pn = bufB;
    for (int t = 0; t < 3; t++) {
        combine_all<<<nsm, NWARP * 32, SMEMC>>>(pc, pn, rowoff, csr, Wl, bl, Wr, t);
        float* tmp = pc; pc = pn; pn = tmp;
    }

    // Phase D: heads
    float* p = pc;
    zero_kernel<<<1, 48>>>(sums, 192);
    colsum_all<<<512, 256>>>(p, sums);
    head_kernel<<<1, 256>>>(sums, Wc1, bc1, Wc2, bc2, out);
    suspect_kernel<<<2048, 256>>>(p, Ws1, bs1, Ws2, bs2, out);
}

// round 8
// speedup vs baseline: 1.2695x; 1.2695x over previous
#include <cuda_runtime.h>
#include <cstdint>

#define NP 200000
#define NO 100000
#define NL 50000
#define NE 1000000
#define HD 64

#define GP2 100000  // person groups (2 nodes each)
#define GO2 50000
#define GL2 25000
#define NCNT (3 * NP + NO + NL)   // 750000

// ---------------- device scratch (static, allowed) ----------------
__device__ float g_nodes[2][(size_t)(NP + NO + NL) * HD];   // double-buffered features
__device__ int   g_csr[5 * NE];                             // single global CSR
__device__ int   g_rowoff[NCNT + 8];                        // global exclusive scan
__device__ int   g_cnt[NCNT];                               // counts, then cursors
__device__ int   g_part[256];                               // scan partials
__device__ float g_sums[3 * HD];                            // column sums

// ---------------- utility kernels ----------------
__global__ void zero_kernel(float* __restrict__ p, size_t n) {
    size_t n4 = n >> 2;
    float4 z = make_float4(0.f, 0.f, 0.f, 0.f);
    for (size_t i = (size_t)blockIdx.x * blockDim.x + threadIdx.x; i < n4;
         i += (size_t)gridDim.x * blockDim.x)
        reinterpret_cast<float4*>(p)[i] = z;
}

__global__ void gather_all(const int* __restrict__ xp, const int* __restrict__ xo,
                           const int* __restrict__ xl,
                           const float* __restrict__ pe, const float* __restrict__ oe,
                           const float* __restrict__ le, float* __restrict__ out) {
    int i = blockIdx.x * blockDim.x + threadIdx.x;
    int total = (NP + NO + NL) * 16;
    if (i >= total) return;
    int node = i >> 4, c = i & 15;
    const int* idx;
    const float* emb;
    int local;
    if (node < NP) { idx = xp; emb = pe; local = node; }
    else if (node < NP + NO) { idx = xo; emb = oe; local = node - NP; }
    else { idx = xl; emb = le; local = node - NP - NO; }
    int e = __ldg(&idx[local]);
    reinterpret_cast<float4*>(out)[(size_t)node * 16 + c] =
        reinterpret_cast<const float4*>(emb)[(size_t)e * 16 + c];
}

// ---------------- CSR build: one pass over all 5 relations ----------------
__global__ void count_all(const int* __restrict__ acts_dst, const int* __restrict__ uses_src,
                          const int* __restrict__ at_src, const int* __restrict__ uses_dst,
                          const int* __restrict__ at_dst, int* __restrict__ cnt) {
    int i = blockIdx.x * blockDim.x + threadIdx.x;
    if (i >= 5 * NE) return;
    int rel = i / NE, e = i - rel * NE;
    int d, off;
    switch (rel) {
        case 0: d = __ldg(&acts_dst[e]); off = 0;           break;
        case 1: d = __ldg(&uses_src[e]); off = NP;          break;
        case 2: d = __ldg(&at_src[e]);   off = 2 * NP;      break;
        case 3: d = __ldg(&uses_dst[e]); off = 3 * NP;      break;
        default: d = __ldg(&at_dst[e]);  off = 3 * NP + NO; break;
    }
    atomicAdd(&cnt[off + d], 1);
}

#define SCHUNK 4096
__global__ void scan_reduce(const int* __restrict__ in, int* __restrict__ part, int n) {
    __shared__ int s[256];
    int base = blockIdx.x * SCHUNK;
    int acc = 0;
    for (int i = threadIdx.x; i < SCHUNK; i += 256) {
        int idx = base + i;
        if (idx < n) acc += in[idx];
    }
    s[threadIdx.x] = acc;
    __syncthreads();
    for (int off = 128; off; off >>= 1) {
        if (threadIdx.x < off) s[threadIdx.x] += s[threadIdx.x + off];
        __syncthreads();
    }
    if (threadIdx.x == 0) part[blockIdx.x] = s[0];
}

// block-parallel exclusive scan of <=256 partials
__global__ void scan_part(int* part, int nb) {
    int tid = threadIdx.x;
    int v = tid < nb ? part[tid] : 0;
    int lane = tid & 31, wp = tid >> 5;
    int x = v;
#pragma unroll
    for (int off = 1; off < 32; off <<= 1) {
        int y = __shfl_up_sync(0xffffffffu, x, off);
        if (lane >= off) x += y;
    }
    __shared__ int ws[8];
    if (lane == 31) ws[wp] = x;
    __syncthreads();
    if (tid == 0) {
        int run = 0;
        for (int i = 0; i < 8; i++) { int t = ws[i]; ws[i] = run; run += t; }
    }
    __syncthreads();
    int incl = x + ws[wp];
    if (tid < nb) part[tid] = incl - v;
    if (tid == nb - 1) part[nb] = incl;
}

__global__ void scan_write(const int* __restrict__ in, const int* __restrict__ part,
                           int* __restrict__ ro, int n, int nb) {
    __shared__ int wsum[8];
    int base = blockIdx.x * SCHUNK;
    int vals[16];
    int tsum = 0;
    int tb = base + threadIdx.x * 16;
#pragma unroll
    for (int j = 0; j < 16; j++) {
        int idx = tb + j;
        int v = (idx < n) ? in[idx] : 0;
        vals[j] = tsum;
        tsum += v;
    }
    int lane = threadIdx.x & 31, wp = threadIdx.x >> 5;
    int xs = tsum;
#pragma unroll
    for (int off = 1; off < 32; off <<= 1) {
        int y = __shfl_up_sync(0xffffffffu, xs, off);
        if (lane >= off) xs += y;
    }
    if (lane == 31) wsum[wp] = xs;
    int wex = xs - tsum;
    __syncthreads();
    if (threadIdx.x == 0) {
        int run = 0;
        for (int i = 0; i < 8; i++) { int v = wsum[i]; wsum[i] = run; run += v; }
    }
    __syncthreads();
    int off0 = part[blockIdx.x] + wsum[wp] + wex;
#pragma unroll
    for (int j = 0; j < 16; j++) {
        int idx = tb + j;
        if (idx < n) ro[idx] = off0 + vals[j];
    }
    if (blockIdx.x == 0 && threadIdx.x == 0) ro[n] = part[nb];
}

__global__ void copy_int(const int* __restrict__ src, int* __restrict__ dst, int n4) {
    int i = blockIdx.x * blockDim.x + threadIdx.x;
    if (i < n4) reinterpret_cast<int4*>(dst)[i] = reinterpret_cast<const int4*>(src)[i];
}

__global__ void fill_all(const int* __restrict__ acts_src, const int* __restrict__ acts_dst,
                         const int* __restrict__ uses_src, const int* __restrict__ uses_dst,
                         const int* __restrict__ at_src, const int* __restrict__ at_dst,
                         int* __restrict__ cur, int* __restrict__ csr) {
    int i = blockIdx.x * blockDim.x + threadIdx.x;
    if (i >= 5 * NE) return;
    int rel = i / NE, e = i - rel * NE;
    int d, s, off;
    switch (rel) {
        case 0: d = __ldg(&acts_dst[e]); s = __ldg(&acts_src[e]); off = 0;           break;
        case 1: d = __ldg(&uses_src[e]); s = __ldg(&uses_dst[e]); off = NP;          break;
        case 2: d = __ldg(&at_src[e]);   s = __ldg(&at_dst[e]);   off = 2 * NP;      break;
        case 3: d = __ldg(&uses_dst[e]); s = __ldg(&uses_src[e]); off = 3 * NP;      break;
        default: d = __ldg(&at_dst[e]);  s = __ldg(&at_src[e]);   off = 3 * NP + NO; break;
    }
    int pos = atomicAdd(&cur[off + d], 1);
    csr[pos] = s;
}

// ---------------- packed f32x2 FMA (e comes pre-duplicated from smem) ----------------
__device__ __forceinline__ void fma2p(unsigned long long& acc, unsigned long long w,
                                      unsigned long long e) {
    asm("fma.rn.f32x2 %0, %1, %2, %0;" : "+l"(acc) : "l"(w), "l"(e));
}

// ---------------- unified fused aggregate + SAGE combine ----------------
#define WSTRIDE 66                    // padded row stride (floats)
#define WMAT (64 * WSTRIDE)           // 4224 floats per matrix
#define NWARP 16                      // warps per block
#define STSLOT 128                    // duplicated stage row: 64 values x2
#define STWARP (8 * STSLOT)           // 2 nodes * 4 slots * 128 floats = 4KB/warp

template <int NR, int MA, int MB, int MC, int MD>
__device__ __forceinline__ void do_group(
    int nd0, int n, const float* __restrict__ x, float* __restrict__ out,
    const float* s0, const float* s1, const float* s2,
    const int* ro0, const int* ro1, const int* ro2,
    const int* __restrict__ csr,
    const float* __restrict__ WT, const float* __restrict__ bias,
    float* __restrict__ st, int lane, float inv) {
    constexpr int mats[4] = {MA, MB, MC, MD};
    const float* srcs[3] = {s0, s1, s2};
    const int* ros[3] = {ro0, ro1, ro2};
    float2 xv[2];
#pragma unroll
    for (int m = 0; m < 2; m++) {
        int nd = nd0 + m;
        bool act = nd < n;
        int ndc = act ? nd : 0;
#pragma unroll
        for (int r = 0; r < NR; r++) {
            int base = __ldg(&ros[r][ndc]);
            int deg = act ? (__ldg(&ros[r][ndc + 1]) - base) : 0;
            const float* S = srcs[r];
            const int* C = csr + base;
            float sx = 0.f, sy = 0.f;
            int i = 0;
            for (; i + 8 <= deg; i += 8) {
                int ix[8];
#pragma unroll
                for (int j = 0; j < 8; j++) ix[j] = __ldg(C + i + j);
                float2 v[8];
#pragma unroll
                for (int j = 0; j < 8; j++)
                    v[j] = *reinterpret_cast<const float2*>(S + (size_t)ix[j] * HD + 2 * lane);
#pragma unroll
                for (int j = 0; j < 8; j++) { sx += v[j].x; sy += v[j].y; }
            }
            for (; i + 4 <= deg; i += 4) {
                int n0 = __ldg(C + i), n1 = __ldg(C + i + 1);
                int n2 = __ldg(C + i + 2), n3 = __ldg(C + i + 3);
                float2 v0 = *reinterpret_cast<const float2*>(S + (size_t)n0 * HD + 2 * lane);
                float2 v1 = *reinterpret_cast<const float2*>(S + (size_t)n1 * HD + 2 * lane);
                float2 v2 = *reinterpret_cast<const float2*>(S + (size_t)n2 * HD + 2 * lane);
                float2 v3 = *reinterpret_cast<const float2*>(S + (size_t)n3 * HD + 2 * lane);
                sx += (v0.x + v1.x) + (v2.x + v3.x);
                sy += (v0.y + v1.y) + (v2.y + v3.y);
            }
            for (; i < deg; i++) {
                int nn = __ldg(C + i);
                float2 v = *reinterpret_cast<const float2*>(S + (size_t)nn * HD + 2 * lane);
                sx += v.x; sy += v.y;
            }
            float ic = deg > 0 ? 1.0f / (float)deg : 0.f;
            float4 dup = make_float4(sx * ic, sx * ic, sy * ic, sy * ic);
            *reinterpret_cast<float4*>(st + (m * (NR + 1) + r) * STSLOT + 4 * lane) = dup;
        }
        float2 xx = *reinterpret_cast<const float2*>(x + (size_t)ndc * HD + 2 * lane);
        xv[m] = xx;
        float4 dup = make_float4(xx.x, xx.x, xx.y, xx.y);
        *reinterpret_cast<float4*>(st + (m * (NR + 1) + NR) * STSLOT + 4 * lane) = dup;
    }
    __syncwarp();

    float2 bb = *reinterpret_cast<const float2*>(bias + 2 * lane);
    unsigned long long accb;
    asm("mov.b64 %0, {%1, %2};" : "=l"(accb) : "f"(bb.x), "f"(bb.y));
    unsigned long long acc0 = accb, acc1 = accb;
#pragma unroll 8
    for (int k0 = 0; k0 < 64; k0 += 2) {
#pragma unroll
        for (int mi = 0; mi < NR + 1; mi++) {
            const float* Wm = WT + mats[mi] * WMAT;
            unsigned long long w0 = *reinterpret_cast<const unsigned long long*>(
                Wm + k0 * WSTRIDE + 2 * lane);
            unsigned long long w1 = *reinterpret_cast<const unsigned long long*>(
                Wm + (k0 + 1) * WSTRIDE + 2 * lane);
            const float* sb = st + mi * STSLOT + 2 * k0;
            ulonglong2 e0 = *reinterpret_cast<const ulonglong2*>(sb);
            ulonglong2 e1 = *reinterpret_cast<const ulonglong2*>(sb + (NR + 1) * STSLOT);
            fma2p(acc0, w0, e0.x); fma2p(acc0, w1, e0.y);
            fma2p(acc1, w0, e1.x); fma2p(acc1, w1, e1.y);
        }
    }
#pragma unroll
    for (int m = 0; m < 2; m++) {
        int nd = nd0 + m;
        if (nd >= n) break;
        unsigned long long a = m == 0 ? acc0 : acc1;
        float ax, ay;
        asm("mov.b64 {%0, %1}, %2;" : "=f"(ax), "=f"(ay) : "l"(a));
        float2 res;
        res.x = fmaxf(ax * inv, 0.f) + xv[m].x;
        res.y = fmaxf(ay * inv, 0.f) + xv[m].y;
        *reinterpret_cast<float2*>(out + (size_t)nd * HD + 2 * lane) = res;
    }
    __syncwarp();
}

// smem: 8 mats * WMAT + 192 bias + NWARP * STWARP stage  (= 201,472 B)
#define SMEMC ((8 * WMAT + 192 + NWARP * STWARP) * 4)

__global__ void __launch_bounds__(NWARP * 32, 1) combine_all(
    const float* __restrict__ xin, float* __restrict__ xout,
    const int* __restrict__ rowoff, const int* __restrict__ csr,
    const float* __restrict__ Wl, const float* __restrict__ blv,
    const float* __restrict__ Wr, int t) {
    extern __shared__ float sm[];
    float* WT   = sm;                   // 8 mats, stride-padded, transposed [k][c]
    float* bias = WT + 8 * WMAT;        // 3 * 64
    float* stage = bias + 192;          // NWARP * STWARP (duplicated pairs)

    const int tid = threadIdx.x;
    const int nthr = NWARP * 32;
    const float* WlB = Wl + (size_t)t * 5 * 4096;
    const float* WrB = Wr + (size_t)t * 5 * 4096;
    // mats 0..4 = Wl[t][0..4]^T
    for (int i = tid; i < 5 * 4096; i += nthr) {
        int m = i >> 12, j = i & 4095;
        int c = j >> 6, k = j & 63;
        WT[m * WMAT + k * WSTRIDE + c] = WlB[i];
    }
    // mat 5 = (Wr0+Wr2+Wr4)^T, mat 6 = Wr1^T, mat 7 = Wr3^T
    for (int i = tid; i < 4096; i += nthr) {
        int c = i >> 6, k = i & 63;
        WT[5 * WMAT + k * WSTRIDE + c] = WrB[i] + WrB[2 * 4096 + i] + WrB[4 * 4096 + i];
        WT[6 * WMAT + k * WSTRIDE + c] = WrB[4096 + i];
        WT[7 * WMAT + k * WSTRIDE + c] = WrB[3 * 4096 + i];
    }
    if (tid < 64) {
        const float* b = blv + (size_t)t * 5 * 64;
        bias[tid]       = b[tid] + b[128 + tid] + b[256 + tid];
        bias[64 + tid]  = b[64 + tid];
        bias[128 + tid] = b[192 + tid];
    }
    __syncthreads();

    const int lane = tid & 31, w = tid >> 5;
    float* st = stage + w * STWARP;
    const float* P  = xin;
    const float* O  = xin + (size_t)NP * HD;
    const float* Lc = xin + (size_t)(NP + NO) * HD;

    for (int g = blockIdx.x * NWARP + w; g < GP2 + GO2 + GL2; g += gridDim.x * NWARP) {
        if (g < GP2) {
            do_group<3, 0, 2, 4, 5>(g * 2, NP, P, xout,
                P, O, Lc, rowoff, rowoff + NP, rowoff + 2 * NP, csr,
                WT, bias, st, lane, 1.0f / 3.0f);
        } else if (g < GP2 + GO2) {
            do_group<1, 1, 6, 0, 0>((g - GP2) * 2, NO, O, xout + (size_t)NP * HD,
                P, P, P, rowoff + 3 * NP, rowoff + 3 * NP, rowoff + 3 * NP, csr,
                WT, bias + 64, st, lane, 1.0f);
        } else {
            do_group<1, 3, 7, 0, 0>((g - GP2 - GO2) * 2, NL, Lc, xout + (size_t)(NP + NO) * HD,
                P, P, P, rowoff + 3 * NP + NO, rowoff + 3 * NP + NO, rowoff + 3 * NP + NO, csr,
                WT, bias + 128, st, lane, 1.0f);
        }
    }
}

// ---------------- column sums over all node types in one pass ----------------
__global__ void colsum_all(const float* __restrict__ x, float* __restrict__ sums) {
    const int lane = threadIdx.x & 31;
    const int w = (blockIdx.x * blockDim.x + threadIdx.x) >> 5;
    const int nw = (gridDim.x * blockDim.x) >> 5;
    float2 a0 = make_float2(0.f, 0.f), a1 = a0, a2 = a0;
    for (int r = w; r < NP + NO + NL; r += nw) {
        float2 v = *reinterpret_cast<const float2*>(x + (size_t)r * HD + 2 * lane);
        if (r < NP)          { a0.x += v.x; a0.y += v.y; }
        else if (r < NP + NO){ a1.x += v.x; a1.y += v.y; }
        else                 { a2.x += v.x; a2.y += v.y; }
    }
    asm volatile("red.global.add.v2.f32 [%0], {%1, %2};"
                 :: "l"(sums + 2 * lane), "f"(a0.x), "f"(a0.y) : "memory");
    asm volatile("red.global.add.v2.f32 [%0], {%1, %2};"
                 :: "l"(sums + 64 + 2 * lane), "f"(a1.x), "f"(a1.y) : "memory");
    asm volatile("red.global.add.v2.f32 [%0], {%1, %2};"
                 :: "l"(sums + 128 + 2 * lane), "f"(a2.x), "f"(a2.y) : "memory");
}

// ---------------- crime head (tiny) ----------------
__global__ void head_kernel(const float* __restrict__ gsum,
                            const float* __restrict__ Wc1, const float* __restrict__ bc1,
                            const float* __restrict__ Wc2, const float* __restrict__ bc2,
                            float* __restrict__ out) {
    __shared__ float g[192];
    __shared__ float h[64];
    int tid = threadIdx.x;
    if (tid < 192) {
        float nrm = tid < 64 ? (1.f / NP) : (tid < 128 ? (1.f / NO) : (1.f / NL));
        g[tid] = gsum[tid] * nrm;
    }
    __syncthreads();
    if (tid < 64) {
        float a = bc1[tid];
        for (int k = 0; k < 192; k++) a = fmaf(g[k], Wc1[tid * 192 + k], a);
        h[tid] = fmaxf(a, 0.f);
    }
    __syncthreads();
    if (tid < 20) {
        float a = bc2[tid];
        for (int k = 0; k < 64; k++) a = fmaf(h[k], Wc2[tid * 64 + k], a);
        out[tid] = a;
    }
}

// ---------------- suspect head: per-person MLP 64->32->1 ----------------
__global__ void __launch_bounds__(256) suspect_kernel(
    const float* __restrict__ p, const float* __restrict__ Ws1, const float* __restrict__ bs1,
    const float* __restrict__ Ws2, const float* __restrict__ bs2, float* __restrict__ out) {
    __shared__ float W1T[64 * 32];
    __shared__ float w2[32], b1[32];
    __shared__ float stage[8][64];
    int tid = threadIdx.x;
    for (int i = tid; i < 2048; i += 256) {
        int j = i >> 6, k = i & 63;
        W1T[k * 32 + j] = Ws1[i];
    }
    if (tid < 32) { w2[tid] = Ws2[tid]; b1[tid] = bs1[tid]; }
    __syncthreads();
    const float b2 = __ldg(bs2);
    const int lane = tid & 31, w = tid >> 5;
    const int wg = blockIdx.x * 8 + w;
    const int nw = gridDim.x * 8;
    for (int nd = wg; nd < NP; nd += nw) {
        float2 v = *reinterpret_cast<const float2*>(p + (size_t)nd * HD + 2 * lane);
        stage[w][2 * lane] = v.x; stage[w][2 * lane + 1] = v.y;
        __syncwarp();
        float acc = b1[lane];
#pragma unroll 8
        for (int k = 0; k < 64; k++)
            acc = fmaf(stage[w][k], W1T[k * 32 + lane], acc);
        float s = fmaxf(acc, 0.f) * w2[lane];
#pragma unroll
        for (int off = 16; off; off >>= 1) s += __shfl_xor_sync(0xffffffffu, s, off);
        if (lane == 0) out[20 + nd] = s + b2;
        __syncwarp();
    }
}

// ---------------- orchestration ----------------
extern "C" void kernel_launch(void* const* d_in, const int* in_sizes, int n_in,
                              void* d_out, int out_size) {
    const int* x_person   = (const int*)d_in[0];
    const int* x_object   = (const int*)d_in[1];
    const int* x_location = (const int*)d_in[2];
    const int* acts_src = (const int*)d_in[3];
    const int* acts_dst = (const int*)d_in[4];
    const int* uses_src = (const int*)d_in[5];
    const int* uses_dst = (const int*)d_in[6];
    const int* at_src   = (const int*)d_in[7];
    const int* at_dst   = (const int*)d_in[8];
    const float* person_emb   = (const float*)d_in[9];
    const float* object_emb   = (const float*)d_in[10];
    const float* location_emb = (const float*)d_in[11];
    const float* Wl  = (const float*)d_in[12];
    const float* bl  = (const float*)d_in[13];
    const float* Wr  = (const float*)d_in[14];
    const float* Wc1 = (const float*)d_in[15];
    const float* bc1 = (const float*)d_in[16];
    const float* Wc2 = (const float*)d_in[17];
    const float* bc2 = (const float*)d_in[18];
    const float* Ws1 = (const float*)d_in[19];
    const float* bs1 = (const float*)d_in[20];
    const float* Ws2 = (const float*)d_in[21];
    const float* bs2 = (const float*)d_in[22];
    float* out = (float*)d_out;

    float* nodes  = nullptr; cudaGetSymbolAddress((void**)&nodes, g_nodes);
    int*   csr    = nullptr; cudaGetSymbolAddress((void**)&csr, g_csr);
    int*   rowoff = nullptr; cudaGetSymbolAddress((void**)&rowoff, g_rowoff);
    int*   cnt    = nullptr; cudaGetSymbolAddress((void**)&cnt, g_cnt);
    int*   part   = nullptr; cudaGetSymbolAddress((void**)&part, g_part);
    float* sums   = nullptr; cudaGetSymbolAddress((void**)&sums, g_sums);

    int nsm = 148;
    cudaDeviceGetAttribute(&nsm, cudaDevAttrMultiProcessorCount, 0);

    const size_t NODESZ = (size_t)(NP + NO + NL) * HD;
    float* bufA = nodes;
    float* bufB = nodes + NODESZ;

    cudaFuncSetAttribute(combine_all, cudaFuncAttributeMaxDynamicSharedMemorySize, SMEMC);

    // Phase A: embedding gathers (all node types, one launch)
    gather_all<<<((NP + NO + NL) * 16 + 255) / 256, 256>>>(
        x_person, x_object, x_location, person_emb, object_emb, location_emb, bufA);

    // Phase B: global CSR build
    zero_kernel<<<256, 256>>>((float*)cnt, (size_t)NCNT);
    count_all<<<(5 * NE + 255) / 256, 256>>>(acts_dst, uses_src, at_src, uses_dst, at_dst, cnt);
    const int NB = (NCNT + SCHUNK - 1) / SCHUNK;   // 184
    scan_reduce<<<NB, 256>>>(cnt, part, NCNT);
    scan_part<<<1, 256>>>(part, NB);
    scan_write<<<NB, 256>>>(cnt, part, rowoff, NCNT, NB);
    copy_int<<<(NCNT / 4 + 255) / 256, 256>>>(rowoff, cnt, NCNT / 4);   // cursors = rowoff
    fill_all<<<(5 * NE + 255) / 256, 256>>>(acts_src, acts_dst, uses_src, uses_dst,
                                            at_src, at_dst, cnt, csr);

    // Phase C: 3 GNN layers, one unified persistent launch per layer
    float* pc = bufA;
    float* pn = bufB;
    for (int t = 0; t < 3; t++) {
        combine_all<<<nsm, NWARP * 32, SMEMC>>>(pc, pn, rowoff, csr, Wl, bl, Wr, t);
        float* tmp = pc; pc = pn; pn = tmp;
    }

    // Phase D: heads
    float* p = pc;
    zero_kernel<<<1, 48>>>(sums, 192);
    colsum_all<<<512, 256>>>(p, sums);
    head_kernel<<<1, 256>>>(sums, Wc1, bc1, Wc2, bc2, out);
    suspect_kernel<<<2048, 256>>>(p, Ws1, bs1, Ws2, bs2, out);
}

// round 9
// speedup vs baseline: 1.3628x; 1.0735x over previous
#include <cuda_runtime.h>
#include <cstdint>

#define NP 200000
#define NO 100000
#define NL 50000
#define NE 1000000
#define HD 64

#define GP 50000   // person groups (4 nodes each)
#define GO 25000
#define GL 12500
#define NCNT (3 * NP + NO + NL)   // 750000

// ---------------- device scratch (static, allowed) ----------------
__device__ float g_nodes[2][(size_t)(NP + NO + NL) * HD];   // double-buffered features
__device__ int   g_csr[5 * NE];                             // single global CSR
__device__ int   g_rowoff[NCNT + 8];                        // global exclusive scan
__device__ int   g_cnt[NCNT];                               // counts, then cursors
__device__ int   g_part[256];                               // scan partials
__device__ float g_sums[3 * HD];                            // column sums

// ---------------- utility kernels ----------------
__global__ void zero_kernel(float* __restrict__ p, size_t n) {
    size_t n4 = n >> 2;
    float4 z = make_float4(0.f, 0.f, 0.f, 0.f);
    for (size_t i = (size_t)blockIdx.x * blockDim.x + threadIdx.x; i < n4;
         i += (size_t)gridDim.x * blockDim.x)
        reinterpret_cast<float4*>(p)[i] = z;
}

__global__ void gather_all(const int* __restrict__ xp, const int* __restrict__ xo,
                           const int* __restrict__ xl,
                           const float* __restrict__ pe, const float* __restrict__ oe,
                           const float* __restrict__ le, float* __restrict__ out) {
    int i = blockIdx.x * blockDim.x + threadIdx.x;
    int total = (NP + NO + NL) * 16;
    if (i >= total) return;
    int node = i >> 4, c = i & 15;
    const int* idx;
    const float* emb;
    int local;
    if (node < NP) { idx = xp; emb = pe; local = node; }
    else if (node < NP + NO) { idx = xo; emb = oe; local = node - NP; }
    else { idx = xl; emb = le; local = node - NP - NO; }
    int e = __ldg(&idx[local]);
    reinterpret_cast<float4*>(out)[(size_t)node * 16 + c] =
        reinterpret_cast<const float4*>(emb)[(size_t)e * 16 + c];
}

// ---------------- CSR build: one pass over all 5 relations ----------------
__global__ void count_all(const int* __restrict__ acts_dst, const int* __restrict__ uses_src,
                          const int* __restrict__ at_src, const int* __restrict__ uses_dst,
                          const int* __restrict__ at_dst, int* __restrict__ cnt) {
    int i = blockIdx.x * blockDim.x + threadIdx.x;
    if (i >= 5 * NE) return;
    int rel = i / NE, e = i - rel * NE;
    int d, off;
    switch (rel) {
        case 0: d = __ldg(&acts_dst[e]); off = 0;           break;
        case 1: d = __ldg(&uses_src[e]); off = NP;          break;
        case 2: d = __ldg(&at_src[e]);   off = 2 * NP;      break;
        case 3: d = __ldg(&uses_dst[e]); off = 3 * NP;      break;
        default: d = __ldg(&at_dst[e]);  off = 3 * NP + NO; break;
    }
    atomicAdd(&cnt[off + d], 1);
}

#define SCHUNK 4096
__global__ void scan_reduce(const int* __restrict__ in, int* __restrict__ part, int n) {
    __shared__ int s[256];
    int base = blockIdx.x * SCHUNK;
    int acc = 0;
    for (int i = threadIdx.x; i < SCHUNK; i += 256) {
        int idx = base + i;
        if (idx < n) acc += in[idx];
    }
    s[threadIdx.x] = acc;
    __syncthreads();
    for (int off = 128; off; off >>= 1) {
        if (threadIdx.x < off) s[threadIdx.x] += s[threadIdx.x + off];
        __syncthreads();
    }
    if (threadIdx.x == 0) part[blockIdx.x] = s[0];
}

// block-parallel exclusive scan of <=256 partials
__global__ void scan_part(int* part, int nb) {
    int tid = threadIdx.x;
    int v = tid < nb ? part[tid] : 0;
    int lane = tid & 31, wp = tid >> 5;
    int x = v;
#pragma unroll
    for (int off = 1; off < 32; off <<= 1) {
        int y = __shfl_up_sync(0xffffffffu, x, off);
        if (lane >= off) x += y;
    }
    __shared__ int ws[8];
    if (lane == 31) ws[wp] = x;
    __syncthreads();
    if (tid == 0) {
        int run = 0;
        for (int i = 0; i < 8; i++) { int t = ws[i]; ws[i] = run; run += t; }
    }
    __syncthreads();
    int incl = x + ws[wp];
    if (tid < nb) part[tid] = incl - v;
    if (tid == nb - 1) part[nb] = incl;
}

__global__ void scan_write(const int* __restrict__ in, const int* __restrict__ part,
                           int* __restrict__ ro, int n, int nb) {
    __shared__ int wsum[8];
    int base = blockIdx.x * SCHUNK;
    int vals[16];
    int tsum = 0;
    int tb = base + threadIdx.x * 16;
#pragma unroll
    for (int j = 0; j < 16; j++) {
        int idx = tb + j;
        int v = (idx < n) ? in[idx] : 0;
        vals[j] = tsum;
        tsum += v;
    }
    int lane = threadIdx.x & 31, wp = threadIdx.x >> 5;
    int xs = tsum;
#pragma unroll
    for (int off = 1; off < 32; off <<= 1) {
        int y = __shfl_up_sync(0xffffffffu, xs, off);
        if (lane >= off) xs += y;
    }
    if (lane == 31) wsum[wp] = xs;
    int wex = xs - tsum;
    __syncthreads();
    if (threadIdx.x == 0) {
        int run = 0;
        for (int i = 0; i < 8; i++) { int v = wsum[i]; wsum[i] = run; run += v; }
    }
    __syncthreads();
    int off0 = part[blockIdx.x] + wsum[wp] + wex;
#pragma unroll
    for (int j = 0; j < 16; j++) {
        int idx = tb + j;
        if (idx < n) ro[idx] = off0 + vals[j];
    }
    if (blockIdx.x == 0 && threadIdx.x == 0) ro[n] = part[nb];
}

__global__ void copy_int(const int* __restrict__ src, int* __restrict__ dst, int n4) {
    int i = blockIdx.x * blockDim.x + threadIdx.x;
    if (i < n4) reinterpret_cast<int4*>(dst)[i] = reinterpret_cast<const int4*>(src)[i];
}

__global__ void fill_all(const int* __restrict__ acts_src, const int* __restrict__ acts_dst,
                         const int* __restrict__ uses_src, const int* __restrict__ uses_dst,
                         const int* __restrict__ at_src, const int* __restrict__ at_dst,
                         int* __restrict__ cur, int* __restrict__ csr) {
    int i = blockIdx.x * blockDim.x + threadIdx.x;
    if (i >= 5 * NE) return;
    int rel = i / NE, e = i - rel * NE;
    int d, s, off;
    switch (rel) {
        case 0: d = __ldg(&acts_dst[e]); s = __ldg(&acts_src[e]); off = 0;           break;
        case 1: d = __ldg(&uses_src[e]); s = __ldg(&uses_dst[e]); off = NP;          break;
        case 2: d = __ldg(&at_src[e]);   s = __ldg(&at_dst[e]);   off = 2 * NP;      break;
        case 3: d = __ldg(&uses_dst[e]); s = __ldg(&uses_src[e]); off = 3 * NP;      break;
        default: d = __ldg(&at_dst[e]);  s = __ldg(&at_src[e]);   off = 3 * NP + NO; break;
    }
    int pos = atomicAdd(&cur[off + d], 1);
    csr[pos] = s;
}

// ---------------- packed f32x2 FMA ----------------
__device__ __forceinline__ void fma2p(unsigned long long& acc, unsigned long long w,
                                      unsigned long long e) {
    asm("fma.rn.f32x2 %0, %1, %2, %0;" : "+l"(acc) : "l"(w), "l"(e));
}

// ---------------- unified fused aggregate + SAGE combine ----------------
#define WSTRIDE 68                    // padded row stride; multiple of 4 for LDS.128
#define WMAT (64 * WSTRIDE)           // 4352 floats per matrix
#define NWARP 16                      // warps per block
#define STWARP 1024                   // 4 nodes * 4 slots * 64 floats per warp

template <int NR, int MA, int MB, int MC, int MD>
__device__ __forceinline__ void do_group(
    int nd0, int n, const float* __restrict__ x, float* __restrict__ out,
    const float* s0, const float* s1, const float* s2,
    const int* ro0, const int* ro1, const int* ro2,
    const int* __restrict__ csr,
    const float* __restrict__ WT, const float* __restrict__ bias,
    float* __restrict__ st, int lane, float inv) {
    constexpr int mats[4] = {MA, MB, MC, MD};
    const float* srcs[3] = {s0, s1, s2};
    const int* ros[3] = {ro0, ro1, ro2};
    // ---- aggregation: lane covers cols (2*lane, 2*lane+1) for all 4 nodes ----
#pragma unroll
    for (int m = 0; m < 4; m++) {
        int nd = nd0 + m;
        bool act = nd < n;
        int ndc = act ? nd : 0;
#pragma unroll
        for (int r = 0; r < NR; r++) {
            int base = __ldg(&ros[r][ndc]);
            int deg = act ? (__ldg(&ros[r][ndc + 1]) - base) : 0;
            const float* S = srcs[r];
            const int* C = csr + base;
            float sx = 0.f, sy = 0.f;
            int i = 0;
            for (; i + 4 <= deg; i += 4) {
                int n0 = __ldg(C + i), n1 = __ldg(C + i + 1);
                int n2 = __ldg(C + i + 2), n3 = __ldg(C + i + 3);
                float2 v0 = *reinterpret_cast<const float2*>(S + (size_t)n0 * HD + 2 * lane);
                float2 v1 = *reinterpret_cast<const float2*>(S + (size_t)n1 * HD + 2 * lane);
                float2 v2 = *reinterpret_cast<const float2*>(S + (size_t)n2 * HD + 2 * lane);
                float2 v3 = *reinterpret_cast<const float2*>(S + (size_t)n3 * HD + 2 * lane);
                sx += (v0.x + v1.x) + (v2.x + v3.x);
                sy += (v0.y + v1.y) + (v2.y + v3.y);
            }
            for (; i < deg; i++) {
                int nn = __ldg(C + i);
                float2 v = *reinterpret_cast<const float2*>(S + (size_t)nn * HD + 2 * lane);
                sx += v.x; sy += v.y;
            }
            float ic = deg > 0 ? 1.0f / (float)deg : 0.f;
            st[(m * (NR + 1) + r) * 64 + 2 * lane]     = sx * ic;
            st[(m * (NR + 1) + r) * 64 + 2 * lane + 1] = sy * ic;
        }
        float2 xx = *reinterpret_cast<const float2*>(x + (size_t)ndc * HD + 2 * lane);
        st[(m * (NR + 1) + NR) * 64 + 2 * lane]     = xx.x;
        st[(m * (NR + 1) + NR) * 64 + 2 * lane + 1] = xx.y;
    }
    __syncwarp();

    // ---- matmul: half-warp split. lane handles cols [q4, q4+4) of nodes {h, 2+h}.
    const int q4 = (lane & 15) * 4;
    const int h = lane >> 4;
    float4 bb = *reinterpret_cast<const float4*>(bias + q4);
    unsigned long long b_lo, b_hi;
    asm("mov.b64 %0, {%1, %2};" : "=l"(b_lo) : "f"(bb.x), "f"(bb.y));
    asm("mov.b64 %0, {%1, %2};" : "=l"(b_hi) : "f"(bb.z), "f"(bb.w));
    unsigned long long a0lo = b_lo, a0hi = b_hi;   // node h
    unsigned long long a1lo = b_lo, a1hi = b_hi;   // node 2+h
#pragma unroll 4
    for (int k0 = 0; k0 < 64; k0 += 2) {
#pragma unroll
        for (int mi = 0; mi < NR + 1; mi++) {
            const float* Wm = WT + mats[mi] * WMAT;
            ulonglong2 w0 = *reinterpret_cast<const ulonglong2*>(Wm + k0 * WSTRIDE + q4);
            ulonglong2 w1 = *reinterpret_cast<const ulonglong2*>(Wm + (k0 + 1) * WSTRIDE + q4);
            float2 eA = *reinterpret_cast<const float2*>(st + (h * (NR + 1) + mi) * 64 + k0);
            float2 eB = *reinterpret_cast<const float2*>(st + ((2 + h) * (NR + 1) + mi) * 64 + k0);
            unsigned long long dA0, dA1, dB0, dB1;
            asm("mov.b64 %0, {%1, %1};" : "=l"(dA0) : "f"(eA.x));
            asm("mov.b64 %0, {%1, %1};" : "=l"(dA1) : "f"(eA.y));
            asm("mov.b64 %0, {%1, %1};" : "=l"(dB0) : "f"(eB.x));
            asm("mov.b64 %0, {%1, %1};" : "=l"(dB1) : "f"(eB.y));
            fma2p(a0lo, w0.x, dA0); fma2p(a0hi, w0.y, dA0);
            fma2p(a0lo, w1.x, dA1); fma2p(a0hi, w1.y, dA1);
            fma2p(a1lo, w0.x, dB0); fma2p(a1hi, w0.y, dB0);
            fma2p(a1lo, w1.x, dB1); fma2p(a1hi, w1.y, dB1);
        }
    }
    // ---- epilogue: relu/scale + residual, lane writes float4 per node ----
#pragma unroll
    for (int mm = 0; mm < 2; mm++) {
        int m = h + 2 * mm;
        int nd = nd0 + m;
        if (nd < n) {
            unsigned long long alo = mm ? a1lo : a0lo;
            unsigned long long ahi = mm ? a1hi : a0hi;
            float r0, r1, r2, r3;
            asm("mov.b64 {%0, %1}, %2;" : "=f"(r0), "=f"(r1) : "l"(alo));
            asm("mov.b64 {%0, %1}, %2;" : "=f"(r2), "=f"(r3) : "l"(ahi));
            float4 xr = *reinterpret_cast<const float4*>(st + (m * (NR + 1) + NR) * 64 + q4);
            float4 res;
            res.x = fmaxf(r0 * inv, 0.f) + xr.x;
            res.y = fmaxf(r1 * inv, 0.f) + xr.y;
            res.z = fmaxf(r2 * inv, 0.f) + xr.z;
            res.w = fmaxf(r3 * inv, 0.f) + xr.w;
            *reinterpret_cast<float4*>(out + (size_t)nd * HD + q4) = res;
        }
    }
    __syncwarp();
}

// smem: 8 mats * WMAT + 192 bias + NWARP * STWARP stage  (= 205,568 B)
#define SMEMC ((8 * WMAT + 192 + NWARP * STWARP) * 4)

__global__ void __launch_bounds__(NWARP * 32, 1) combine_all(
    const float* __restrict__ xin, float* __restrict__ xout,
    const int* __restrict__ rowoff, const int* __restrict__ csr,
    const float* __restrict__ Wl, const float* __restrict__ blv,
    const float* __restrict__ Wr, int t) {
    extern __shared__ float sm[];
    float* WT   = sm;                   // 8 mats, stride-padded, transposed [k][c]
    float* bias = WT + 8 * WMAT;        // 3 * 64
    float* stage = bias + 192;          // NWARP * STWARP

    const int tid = threadIdx.x;
    const int nthr = NWARP * 32;
    const float* WlB = Wl + (size_t)t * 5 * 4096;
    const float* WrB = Wr + (size_t)t * 5 * 4096;
    // mats 0..4 = Wl[t][0..4]^T
    for (int i = tid; i < 5 * 4096; i += nthr) {
        int m = i >> 12, j = i & 4095;
        int c = j >> 6, k = j & 63;
        WT[m * WMAT + k * WSTRIDE + c] = WlB[i];
    }
    // mat 5 = (Wr0+Wr2+Wr4)^T, mat 6 = Wr1^T, mat 7 = Wr3^T
    for (int i = tid; i < 4096; i += nthr) {
        int c = i >> 6, k = i & 63;
        WT[5 * WMAT + k * WSTRIDE + c] = WrB[i] + WrB[2 * 4096 + i] + WrB[4 * 4096 + i];
        WT[6 * WMAT + k * WSTRIDE + c] = WrB[4096 + i];
        WT[7 * WMAT + k * WSTRIDE + c] = WrB[3 * 4096 + i];
    }
    if (tid < 64) {
        const float* b = blv + (size_t)t * 5 * 64;
        bias[tid]       = b[tid] + b[128 + tid] + b[256 + tid];
        bias[64 + tid]  = b[64 + tid];
        bias[128 + tid] = b[192 + tid];
    }
    __syncthreads();

    const int lane = tid & 31, w = tid >> 5;
    float* st = stage + w * STWARP;
    const float* P  = xin;
    const float* O  = xin + (size_t)NP * HD;
    const float* Lc = xin + (size_t)(NP + NO) * HD;

    for (int g = blockIdx.x * NWARP + w; g < GP + GO + GL; g += gridDim.x * NWARP) {
        if (g < GP) {
            do_group<3, 0, 2, 4, 5>(g * 4, NP, P, xout,
                P, O, Lc, rowoff, rowoff + NP, rowoff + 2 * NP, csr,
                WT, bias, st, lane, 1.0f / 3.0f);
        } else if (g < GP + GO) {
            do_group<1, 1, 6, 0, 0>((g - GP) * 4, NO, O, xout + (size_t)NP * HD,
                P, P, P, rowoff + 3 * NP, rowoff + 3 * NP, rowoff + 3 * NP, csr,
                WT, bias + 64, st, lane, 1.0f);
        } else {
            do_group<1, 3, 7, 0, 0>((g - GP - GO) * 4, NL, Lc, xout + (size_t)(NP + NO) * HD,
                P, P, P, rowoff + 3 * NP + NO, rowoff + 3 * NP + NO, rowoff + 3 * NP + NO, csr,
                WT, bias + 128, st, lane, 1.0f);
        }
    }
}

// ---------------- column sums over all node types in one pass ----------------
__global__ void colsum_all(const float* __restrict__ x, float* __restrict__ sums) {
    const int lane = threadIdx.x & 31;
    const int w = (blockIdx.x * blockDim.x + threadIdx.x) >> 5;
    const int nw = (gridDim.x * blockDim.x) >> 5;
    float2 a0 = make_float2(0.f, 0.f), a1 = a0, a2 = a0;
    for (int r = w; r < NP + NO + NL; r += nw) {
        float2 v = *reinterpret_cast<const float2*>(x + (size_t)r * HD + 2 * lane);
        if (r < NP)          { a0.x += v.x; a0.y += v.y; }
        else if (r < NP + NO){ a1.x += v.x; a1.y += v.y; }
        else                 { a2.x += v.x; a2.y += v.y; }
    }
    asm volatile("red.global.add.v2.f32 [%0], {%1, %2};"
                 :: "l"(sums + 2 * lane), "f"(a0.x), "f"(a0.y) : "memory");
    asm volatile("red.global.add.v2.f32 [%0], {%1, %2};"
                 :: "l"(sums + 64 + 2 * lane), "f"(a1.x), "f"(a1.y) : "memory");
    asm volatile("red.global.add.v2.f32 [%0], {%1, %2};"
                 :: "l"(sums + 128 + 2 * lane), "f"(a2.x), "f"(a2.y) : "memory");
}

// ---------------- crime head (tiny) ----------------
__global__ void head_kernel(const float* __restrict__ gsum,
                            const float* __restrict__ Wc1, const float* __restrict__ bc1,
                            const float* __restrict__ Wc2, const float* __restrict__ bc2,
                            float* __restrict__ out) {
    __shared__ float g[192];
    __shared__ float h[64];
    int tid = threadIdx.x;
    if (tid < 192) {
        float nrm = tid < 64 ? (1.f / NP) : (tid < 128 ? (1.f / NO) : (1.f / NL));
        g[tid] = gsum[tid] * nrm;
    }
    __syncthreads();
    if (tid < 64) {
        float a = bc1[tid];
        for (int k = 0; k < 192; k++) a = fmaf(g[k], Wc1[tid * 192 + k], a);
        h[tid] = fmaxf(a, 0.f);
    }
    __syncthreads();
    if (tid < 20) {
        float a = bc2[tid];
        for (int k = 0; k < 64; k++) a = fmaf(h[k], Wc2[tid * 64 + k], a);
        out[tid] = a;
    }
}

// ---------------- suspect head: per-person MLP 64->32->1 ----------------
__global__ void __launch_bounds__(256) suspect_kernel(
    const float* __restrict__ p, const float* __restrict__ Ws1, const float* __restrict__ bs1,
    const float* __restrict__ Ws2, const float* __restrict__ bs2, float* __restrict__ out) {
    __shared__ float W1T[64 * 32];
    __shared__ float w2[32], b1[32];
    __shared__ float stage[8][64];
    int tid = threadIdx.x;
    for (int i = tid; i < 2048; i += 256) {
        int j = i >> 6, k = i & 63;
        W1T[k * 32 + j] = Ws1[i];
    }
    if (tid < 32) { w2[tid] = Ws2[tid]; b1[tid] = bs1[tid]; }
    __syncthreads();
    const float b2 = __ldg(bs2);
    const int lane = tid & 31, w = tid >> 5;
    const int wg = blockIdx.x * 8 + w;
    const int nw = gridDim.x * 8;
    for (int nd = wg; nd < NP; nd += nw) {
        float2 v = *reinterpret_cast<const float2*>(p + (size_t)nd * HD + 2 * lane);
        stage[w][2 * lane] = v.x; stage[w][2 * lane + 1] = v.y;
        __syncwarp();
        float acc = b1[lane];
#pragma unroll 8
        for (int k = 0; k < 64; k++)
            acc = fmaf(stage[w][k], W1T[k * 32 + lane], acc);
        float s = fmaxf(acc, 0.f) * w2[lane];
#pragma unroll
        for (int off = 16; off; off >>= 1) s += __shfl_xor_sync(0xffffffffu, s, off);
        if (lane == 0) out[20 + nd] = s + b2;
        __syncwarp();
    }
}

// ---------------- orchestration ----------------
extern "C" void kernel_launch(void* const* d_in, const int* in_sizes, int n_in,
                              void* d_out, int out_size) {
    const int* x_person   = (const int*)d_in[0];
    const int* x_object   = (const int*)d_in[1];
    const int* x_location = (const int*)d_in[2];
    const int* acts_src = (const int*)d_in[3];
    const int* acts_dst = (const int*)d_in[4];
    const int* uses_src = (const int*)d_in[5];
    const int* uses_dst = (const int*)d_in[6];
    const int* at_src   = (const int*)d_in[7];
    const int* at_dst   = (const int*)d_in[8];
    const float* person_emb   = (const float*)d_in[9];
    const float* object_emb   = (const float*)d_in[10];
    const float* location_emb = (const float*)d_in[11];
    const float* Wl  = (const float*)d_in[12];
    const float* bl  = (const float*)d_in[13];
    const float* Wr  = (const float*)d_in[14];
    const float* Wc1 = (const float*)d_in[15];
    const float* bc1 = (const float*)d_in[16];
    const float* Wc2 = (const float*)d_in[17];
    const float* bc2 = (const float*)d_in[18];
    const float* Ws1 = (const float*)d_in[19];
    const float* bs1 = (const float*)d_in[20];
    const float* Ws2 = (const float*)d_in[21];
    const float* bs2 = (const float*)d_in[22];
    float* out = (float*)d_out;

    float* nodes  = nullptr; cudaGetSymbolAddress((void**)&nodes, g_nodes);
    int*   csr    = nullptr; cudaGetSymbolAddress((void**)&csr, g_csr);
    int*   rowoff = nullptr; cudaGetSymbolAddress((void**)&rowoff, g_rowoff);
    int*   cnt    = nullptr; cudaGetSymbolAddress((void**)&cnt, g_cnt);
    int*   part   = nullptr; cudaGetSymbolAddress((void**)&part, g_part);
    float* sums   = nullptr; cudaGetSymbolAddress((void**)&sums, g_sums);

    int nsm = 148;
    cudaDeviceGetAttribute(&nsm, cudaDevAttrMultiProcessorCount, 0);

    const size_t NODESZ = (size_t)(NP + NO + NL) * HD;
    float* bufA = nodes;
    float* bufB = nodes + NODESZ;

    cudaFuncSetAttribute(combine_all, cudaFuncAttributeMaxDynamicSharedMemorySize, SMEMC);

    // Phase A: embedding gathers (all node types, one launch)
    gather_all<<<((NP + NO + NL) * 16 + 255) / 256, 256>>>(
        x_person, x_object, x_location, person_emb, object_emb, location_emb, bufA);

    // Phase B: global CSR build
    zero_kernel<<<256, 256>>>((float*)cnt, (size_t)NCNT);
    count_all<<<(5 * NE + 255) / 256, 256>>>(acts_dst, uses_src, at_src, uses_dst, at_dst, cnt);
    const int NB = (NCNT + SCHUNK - 1) / SCHUNK;   // 184
    scan_reduce<<<NB, 256>>>(cnt, part, NCNT);
    scan_part<<<1, 256>>>(part, NB);
    scan_write<<<NB, 256>>>(cnt, part, rowoff, NCNT, NB);
    copy_int<<<(NCNT / 4 + 255) / 256, 256>>>(rowoff, cnt, NCNT / 4);   // cursors = rowoff
    fill_all<<<(5 * NE + 255) / 256, 256>>>(acts_src, acts_dst, uses_src, uses_dst,
                                            at_src, at_dst, cnt, csr);

    // Phase C: 3 GNN layers, one unified persistent launch per layer
    float* pc = bufA;
    float* pn = bufB;
    for (int t = 0; t < 3; t++) {
        combine_all<<<nsm, NWARP * 32, SMEMC>>>(pc, pn, rowoff, csr, Wl, bl, Wr, t);
        float* tmp = pc; pc = pn; pn = tmp;
    }

    // Phase D: heads
    float* p = pc;
    zero_kernel<<<1, 48>>>(sums, 192);
    colsum_all<<<512, 256>>>(p, sums);
    head_kernel<<<1, 256>>>(sums, Wc1, bc1, Wc2, bc2, out);
    suspect_kernel<<<2048, 256>>>(p, Ws1, bs1, Ws2, bs2, out);
}

// round 13
// speedup vs baseline: 1.9265x; 1.4136x over previous
#include <cuda_runtime.h>
#include <cstdint>

#define NP 200000
#define NO 100000
#define NL 50000
#define NE 1000000
#define HD 64

#define GP 50000   // person groups (4 nodes each)
#define GO 25000
#define GL 12500
#define NCNT (3 * NP + NO + NL)   // 750000

// ---------------- device scratch (static, allowed) ----------------
__device__ float g_nodes[2][(size_t)(NP + NO + NL) * HD];   // double-buffered features
__device__ float g_means[(size_t)NCNT * HD];                // per-slot aggregated means
__device__ int   g_csr[5 * NE];                             // single global CSR
__device__ int   g_rowoff[NCNT + 8];                        // global exclusive scan
__device__ int   g_cnt[NCNT];                               // counts, then cursors
__device__ int   g_part[256];                               // scan partials
__device__ float g_sums[3 * HD];                            // column sums

// ---------------- utility kernels ----------------
__global__ void zero_kernel(float* __restrict__ p, size_t n) {
    size_t n4 = n >> 2;
    float4 z = make_float4(0.f, 0.f, 0.f, 0.f);
    for (size_t i = (size_t)blockIdx.x * blockDim.x + threadIdx.x; i < n4;
         i += (size_t)gridDim.x * blockDim.x)
        reinterpret_cast<float4*>(p)[i] = z;
}

__global__ void gather_all(const int* __restrict__ xp, const int* __restrict__ xo,
                           const int* __restrict__ xl,
                           const float* __restrict__ pe, const float* __restrict__ oe,
                           const float* __restrict__ le, float* __restrict__ out) {
    int i = blockIdx.x * blockDim.x + threadIdx.x;
    int total = (NP + NO + NL) * 16;
    if (i >= total) return;
    int node = i >> 4, c = i & 15;
    const int* idx;
    const float* emb;
    int local;
    if (node < NP) { idx = xp; emb = pe; local = node; }
    else if (node < NP + NO) { idx = xo; emb = oe; local = node - NP; }
    else { idx = xl; emb = le; local = node - NP - NO; }
    int e = __ldg(&idx[local]);
    reinterpret_cast<float4*>(out)[(size_t)node * 16 + c] =
        reinterpret_cast<const float4*>(emb)[(size_t)e * 16 + c];
}

// ---------------- CSR build: one pass over all 5 relations ----------------
__global__ void count_all(const int* __restrict__ acts_dst, const int* __restrict__ uses_src,
                          const int* __restrict__ at_src, const int* __restrict__ uses_dst,
                          const int* __restrict__ at_dst, int* __restrict__ cnt) {
    int i = blockIdx.x * blockDim.x + threadIdx.x;
    if (i >= 5 * NE) return;
    int rel = i / NE, e = i - rel * NE;
    int d, off;
    switch (rel) {
        case 0: d = __ldg(&acts_dst[e]); off = 0;           break;
        case 1: d = __ldg(&uses_src[e]); off = NP;          break;
        case 2: d = __ldg(&at_src[e]);   off = 2 * NP;      break;
        case 3: d = __ldg(&uses_dst[e]); off = 3 * NP;      break;
        default: d = __ldg(&at_dst[e]);  off = 3 * NP + NO; break;
    }
    atomicAdd(&cnt[off + d], 1);
}

#define SCHUNK 4096
__global__ void scan_reduce(const int* __restrict__ in, int* __restrict__ part, int n) {
    __shared__ int s[256];
    int base = blockIdx.x * SCHUNK;
    int acc = 0;
    for (int i = threadIdx.x; i < SCHUNK; i += 256) {
        int idx = base + i;
        if (idx < n) acc += in[idx];
    }
    s[threadIdx.x] = acc;
    __syncthreads();
    for (int off = 128; off; off >>= 1) {
        if (threadIdx.x < off) s[threadIdx.x] += s[threadIdx.x + off];
        __syncthreads();
    }
    if (threadIdx.x == 0) part[blockIdx.x] = s[0];
}

// block-parallel exclusive scan of <=256 partials
__global__ void scan_part(int* part, int nb) {
    int tid = threadIdx.x;
    int v = tid < nb ? part[tid] : 0;
    int lane = tid & 31, wp = tid >> 5;
    int x = v;
#pragma unroll
    for (int off = 1; off < 32; off <<= 1) {
        int y = __shfl_up_sync(0xffffffffu, x, off);
        if (lane >= off) x += y;
    }
    __shared__ int ws[8];
    if (lane == 31) ws[wp] = x;
    __syncthreads();
    if (tid == 0) {
        int run = 0;
        for (int i = 0; i < 8; i++) { int t = ws[i]; ws[i] = run; run += t; }
    }
    __syncthreads();
    int incl = x + ws[wp];
    if (tid < nb) part[tid] = incl - v;
    if (tid == nb - 1) part[nb] = incl;
}

__global__ void scan_write(const int* __restrict__ in, const int* __restrict__ part,
                           int* __restrict__ ro, int n, int nb) {
    __shared__ int wsum[8];
    int base = blockIdx.x * SCHUNK;
    int vals[16];
    int tsum = 0;
    int tb = base + threadIdx.x * 16;
#pragma unroll
    for (int j = 0; j < 16; j++) {
        int idx = tb + j;
        int v = (idx < n) ? in[idx] : 0;
        vals[j] = tsum;
        tsum += v;
    }
    int lane = threadIdx.x & 31, wp = threadIdx.x >> 5;
    int xs = tsum;
#pragma unroll
    for (int off = 1; off < 32; off <<= 1) {
        int y = __shfl_up_sync(0xffffffffu, xs, off);
        if (lane >= off) xs += y;
    }
    if (lane == 31) wsum[wp] = xs;
    int wex = xs - tsum;
    __syncthreads();
    if (threadIdx.x == 0) {
        int run = 0;
        for (int i = 0; i < 8; i++) { int v = wsum[i]; wsum[i] = run; run += v; }
    }
    __syncthreads();
    int off0 = part[blockIdx.x] + wsum[wp] + wex;
#pragma unroll
    for (int j = 0; j < 16; j++) {
        int idx = tb + j;
        if (idx < n) ro[idx] = off0 + vals[j];
    }
    if (blockIdx.x == 0 && threadIdx.x == 0) ro[n] = part[nb];
}

__global__ void copy_int(const int* __restrict__ src, int* __restrict__ dst, int n4) {
    int i = blockIdx.x * blockDim.x + threadIdx.x;
    if (i < n4) reinterpret_cast<int4*>(dst)[i] = reinterpret_cast<const int4*>(src)[i];
}

__global__ void fill_all(const int* __restrict__ acts_src, const int* __restrict__ acts_dst,
                         const int* __restrict__ uses_src, const int* __restrict__ uses_dst,
                         const int* __restrict__ at_src, const int* __restrict__ at_dst,
                         int* __restrict__ cur, int* __restrict__ csr) {
    int i = blockIdx.x * blockDim.x + threadIdx.x;
    if (i >= 5 * NE) return;
    int rel = i / NE, e = i - rel * NE;
    int d, s, off;
    switch (rel) {
        case 0: d = __ldg(&acts_dst[e]); s = __ldg(&acts_src[e]); off = 0;           break;
        case 1: d = __ldg(&uses_src[e]); s = __ldg(&uses_dst[e]); off = NP;          break;
        case 2: d = __ldg(&at_src[e]);   s = __ldg(&at_dst[e]);   off = 2 * NP;      break;
        case 3: d = __ldg(&uses_dst[e]); s = __ldg(&uses_src[e]); off = 3 * NP;      break;
        default: d = __ldg(&at_dst[e]);  s = __ldg(&at_src[e]);   off = 3 * NP + NO; break;
    }
    int pos = atomicAdd(&cur[off + d], 1);
    csr[pos] = s;
}

// ---------------- mean aggregation at max occupancy (no smem) ----------------
// slot layout: [0,NP) person<-person  [NP,2NP) person<-object  [2NP,3NP) person<-location
//              [3NP,3NP+NO) object<-person   [3NP+NO,NCNT) location<-person
__global__ void __launch_bounds__(256) agg_all(
    const float* __restrict__ xin, float* __restrict__ means,
    const int* __restrict__ rowoff, const int* __restrict__ csr) {
    const int lane = threadIdx.x & 31;
    const int w = (blockIdx.x * blockDim.x + threadIdx.x) >> 5;
    const int nw = (gridDim.x * blockDim.x) >> 5;
    const float* P = xin;
    const float* O = xin + (size_t)NP * HD;
    const float* L = xin + (size_t)(NP + NO) * HD;
    for (int s = w; s < NCNT; s += nw) {
        const float* S;
        if (s < NP) S = P;
        else if (s < 2 * NP) S = O;
        else if (s < 3 * NP) S = L;
        else S = P;
        int base = __ldg(&rowoff[s]);
        int deg = __ldg(&rowoff[s + 1]) - base;
        const int* C = csr + base;
        float sx = 0.f, sy = 0.f;
        int i = 0;
        for (; i + 4 <= deg; i += 4) {
            int n0 = __ldg(C + i), n1 = __ldg(C + i + 1);
            int n2 = __ldg(C + i + 2), n3 = __ldg(C + i + 3);
            float2 v0 = *reinterpret_cast<const float2*>(S + (size_t)n0 * HD + 2 * lane);
            float2 v1 = *reinterpret_cast<const float2*>(S + (size_t)n1 * HD + 2 * lane);
            float2 v2 = *reinterpret_cast<const float2*>(S + (size_t)n2 * HD + 2 * lane);
            float2 v3 = *reinterpret_cast<const float2*>(S + (size_t)n3 * HD + 2 * lane);
            sx += (v0.x + v1.x) + (v2.x + v3.x);
            sy += (v0.y + v1.y) + (v2.y + v3.y);
        }
        for (; i < deg; i++) {
            int nn = __ldg(C + i);
            float2 v = *reinterpret_cast<const float2*>(S + (size_t)nn * HD + 2 * lane);
            sx += v.x; sy += v.y;
        }
        float ic = deg > 0 ? 1.0f / (float)deg : 0.f;
        float2 r = make_float2(sx * ic, sy * ic);
        *reinterpret_cast<float2*>(means + (size_t)s * HD + 2 * lane) = r;
    }
}

// ---------------- packed f32x2 FMA ----------------
__device__ __forceinline__ void fma2p(unsigned long long& acc, unsigned long long w,
                                      unsigned long long e) {
    asm("fma.rn.f32x2 %0, %1, %2, %0;" : "+l"(acc) : "l"(w), "l"(e));
}

// ---------------- dense SAGE combine on precomputed means ----------------
#define WSTRIDE 68                    // padded row stride; multiple of 4 for LDS.128
#define WMAT (64 * WSTRIDE)           // 4352 floats per matrix
#define NWARP 16                      // warps per block
#define STWARP 1024                   // 4 nodes * 4 slots * 64 floats per warp

template <int NR, int MA, int MB, int MC, int MD>
__device__ __forceinline__ void do_group_mm(
    int nd0, int n, const float* __restrict__ x, float* __restrict__ out,
    const float* __restrict__ means, int sb0, int sb1, int sb2,
    const float* __restrict__ WT, const float* __restrict__ bias,
    float* __restrict__ st, int lane, float inv) {
    constexpr int mats[4] = {MA, MB, MC, MD};
    const int sbs[3] = {sb0, sb1, sb2};
    // ---- stage: coalesced mean/x loads, lane covers cols (2*lane, 2*lane+1) ----
#pragma unroll
    for (int m = 0; m < 4; m++) {
        int nd = nd0 + m;
        int ndc = nd < n ? nd : 0;
#pragma unroll
        for (int r = 0; r < NR; r++) {
            float2 v = *reinterpret_cast<const float2*>(
                means + (size_t)(sbs[r] + ndc) * HD + 2 * lane);
            st[(m * (NR + 1) + r) * 64 + 2 * lane]     = v.x;
            st[(m * (NR + 1) + r) * 64 + 2 * lane + 1] = v.y;
        }
        float2 xx = *reinterpret_cast<const float2*>(x + (size_t)ndc * HD + 2 * lane);
        st[(m * (NR + 1) + NR) * 64 + 2 * lane]     = xx.x;
        st[(m * (NR + 1) + NR) * 64 + 2 * lane + 1] = xx.y;
    }
    __syncwarp();

    // ---- matmul: half-warp split. lane handles cols [q4, q4+4) of nodes {h, 2+h}.
    const int q4 = (lane & 15) * 4;
    const int h = lane >> 4;
    float4 bb = *reinterpret_cast<const float4*>(bias + q4);
    unsigned long long b_lo, b_hi;
    asm("mov.b64 %0, {%1, %2};" : "=l"(b_lo) : "f"(bb.x), "f"(bb.y));
    asm("mov.b64 %0, {%1, %2};" : "=l"(b_hi) : "f"(bb.z), "f"(bb.w));
    unsigned long long a0lo = b_lo, a0hi = b_hi;   // node h
    unsigned long long a1lo = b_lo, a1hi = b_hi;   // node 2+h
#pragma unroll 4
    for (int k0 = 0; k0 < 64; k0 += 2) {
#pragma unroll
        for (int mi = 0; mi < NR + 1; mi++) {
            const float* Wm = WT + mats[mi] * WMAT;
            ulonglong2 w0 = *reinterpret_cast<const ulonglong2*>(Wm + k0 * WSTRIDE + q4);
            ulonglong2 w1 = *reinterpret_cast<const ulonglong2*>(Wm + (k0 + 1) * WSTRIDE + q4);
            float2 eA = *reinterpret_cast<const float2*>(st + (h * (NR + 1) + mi) * 64 + k0);
            float2 eB = *reinterpret_cast<const float2*>(st + ((2 + h) * (NR + 1) + mi) * 64 + k0);
            unsigned long long dA0, dA1, dB0, dB1;
            asm("mov.b64 %0, {%1, %1};" : "=l"(dA0) : "f"(eA.x));
            asm("mov.b64 %0, {%1, %1};" : "=l"(dA1) : "f"(eA.y));
            asm("mov.b64 %0, {%1, %1};" : "=l"(dB0) : "f"(eB.x));
            asm("mov.b64 %0, {%1, %1};" : "=l"(dB1) : "f"(eB.y));
            fma2p(a0lo, w0.x, dA0); fma2p(a0hi, w0.y, dA0);
            fma2p(a0lo, w1.x, dA1); fma2p(a0hi, w1.y, dA1);
            fma2p(a1lo, w0.x, dB0); fma2p(a1hi, w0.y, dB0);
            fma2p(a1lo, w1.x, dB1); fma2p(a1hi, w1.y, dB1);
        }
    }
    // ---- epilogue: relu/scale + residual, lane writes float4 per node ----
#pragma unroll
    for (int mm = 0; mm < 2; mm++) {
        int m = h + 2 * mm;
        int nd = nd0 + m;
        if (nd < n) {
            unsigned long long alo = mm ? a1lo : a0lo;
            unsigned long long ahi = mm ? a1hi : a0hi;
            float r0, r1, r2, r3;
            asm("mov.b64 {%0, %1}, %2;" : "=f"(r0), "=f"(r1) : "l"(alo));
            asm("mov.b64 {%0, %1}, %2;" : "=f"(r2), "=f"(r3) : "l"(ahi));
            float4 xr = *reinterpret_cast<const float4*>(st + (m * (NR + 1) + NR) * 64 + q4);
            float4 res;
            res.x = fmaxf(r0 * inv, 0.f) + xr.x;
            res.y = fmaxf(r1 * inv, 0.f) + xr.y;
            res.z = fmaxf(r2 * inv, 0.f) + xr.z;
            res.w = fmaxf(r3 * inv, 0.f) + xr.w;
            *reinterpret_cast<float4*>(out + (size_t)nd * HD + q4) = res;
        }
    }
    __syncwarp();
}

// smem: 8 mats * WMAT + 192 bias + NWARP * STWARP stage  (= 205,568 B)
#define SMEMC ((8 * WMAT + 192 + NWARP * STWARP) * 4)

__global__ void __launch_bounds__(NWARP * 32, 1) gemm_all(
    const float* __restrict__ xin, float* __restrict__ xout,
    const float* __restrict__ means,
    const float* __restrict__ Wl, const float* __restrict__ blv,
    const float* __restrict__ Wr, int t) {
    extern __shared__ float sm[];
    float* WT   = sm;                   // 8 mats, stride-padded, transposed [k][c]
    float* bias = WT + 8 * WMAT;        // 3 * 64
    float* stage = bias + 192;          // NWARP * STWARP

    const int tid = threadIdx.x;
    const int nthr = NWARP * 32;
    const float* WlB = Wl + (size_t)t * 5 * 4096;
    const float* WrB = Wr + (size_t)t * 5 * 4096;
    // mats 0..4 = Wl[t][0..4]^T
    for (int i = tid; i < 5 * 4096; i += nthr) {
        int m = i >> 12, j = i & 4095;
        int c = j >> 6, k = j & 63;
        WT[m * WMAT + k * WSTRIDE + c] = WlB[i];
    }
    // mat 5 = (Wr0+Wr2+Wr4)^T, mat 6 = Wr1^T, mat 7 = Wr3^T
    for (int i = tid; i < 4096; i += nthr) {
        int c = i >> 6, k = i & 63;
        WT[5 * WMAT + k * WSTRIDE + c] = WrB[i] + WrB[2 * 4096 + i] + WrB[4 * 4096 + i];
        WT[6 * WMAT + k * WSTRIDE + c] = WrB[4096 + i];
        WT[7 * WMAT + k * WSTRIDE + c] = WrB[3 * 4096 + i];
    }
    if (tid < 64) {
        const float* b = blv + (size_t)t * 5 * 64;
        bias[tid]       = b[tid] + b[128 + tid] + b[256 + tid];
        bias[64 + tid]  = b[64 + tid];
        bias[128 + tid] = b[192 + tid];
    }
    __syncthreads();

    const int lane = tid & 31, w = tid >> 5;
    float* st = stage + w * STWARP;
    const float* P  = xin;
    const float* O  = xin + (size_t)NP * HD;
    const float* Lc = xin + (size_t)(NP + NO) * HD;

    for (int g = blockIdx.x * NWARP + w; g < GP + GO + GL; g += gridDim.x * NWARP) {
        if (g < GP) {
            do_group_mm<3, 0, 2, 4, 5>(g * 4, NP, P, xout,
                means, 0, NP, 2 * NP,
                WT, bias, st, lane, 1.0f / 3.0f);
        } else if (g < GP + GO) {
            do_group_mm<1, 1, 6, 0, 0>((g - GP) * 4, NO, O, xout + (size_t)NP * HD,
                means, 3 * NP, 0, 0,
                WT, bias + 64, st, lane, 1.0f);
        } else {
            do_group_mm<1, 3, 7, 0, 0>((g - GP - GO) * 4, NL, Lc, xout + (size_t)(NP + NO) * HD,
                means, 3 * NP + NO, 0, 0,
                WT, bias + 128, st, lane, 1.0f);
        }
    }
}

// ---------------- column sums over all node types in one pass ----------------
__global__ void colsum_all(const float* __restrict__ x, float* __restrict__ sums) {
    const int lane = threadIdx.x & 31;
    const int w = (blockIdx.x * blockDim.x + threadIdx.x) >> 5;
    const int nw = (gridDim.x * blockDim.x) >> 5;
    float2 a0 = make_float2(0.f, 0.f), a1 = a0, a2 = a0;
    for (int r = w; r < NP + NO + NL; r += nw) {
        float2 v = *reinterpret_cast<const float2*>(x + (size_t)r * HD + 2 * lane);
        if (r < NP)          { a0.x += v.x; a0.y += v.y; }
        else if (r < NP + NO){ a1.x += v.x; a1.y += v.y; }
        else                 { a2.x += v.x; a2.y += v.y; }
    }
    asm volatile("red.global.add.v2.f32 [%0], {%1, %2};"
                 :: "l"(sums + 2 * lane), "f"(a0.x), "f"(a0.y) : "memory");
    asm volatile("red.global.add.v2.f32 [%0], {%1, %2};"
                 :: "l"(sums + 64 + 2 * lane), "f"(a1.x), "f"(a1.y) : "memory");
    asm volatile("red.global.add.v2.f32 [%0], {%1, %2};"
                 :: "l"(sums + 128 + 2 * lane), "f"(a2.x), "f"(a2.y) : "memory");
}

// ---------------- crime head (tiny) ----------------
__global__ void head_kernel(const float* __restrict__ gsum,
                            const float* __restrict__ Wc1, const float* __restrict__ bc1,
                            const float* __restrict__ Wc2, const float* __restrict__ bc2,
                            float* __restrict__ out) {
    __shared__ float g[192];
    __shared__ float h[64];
    int tid = threadIdx.x;
    if (tid < 192) {
        float nrm = tid < 64 ? (1.f / NP) : (tid < 128 ? (1.f / NO) : (1.f / NL));
        g[tid] = gsum[tid] * nrm;
    }
    __syncthreads();
    if (tid < 64) {
        float a = bc1[tid];
        for (int k = 0; k < 192; k++) a = fmaf(g[k], Wc1[tid * 192 + k], a);
        h[tid] = fmaxf(a, 0.f);
    }
    __syncthreads();
    if (tid < 20) {
        float a = bc2[tid];
        for (int k = 0; k < 64; k++) a = fmaf(h[k], Wc2[tid * 64 + k], a);
        out[tid] = a;
    }
}

// ---------------- suspect head: per-person MLP 64->32->1 ----------------
__global__ void __launch_bounds__(256) suspect_kernel(
    const float* __restrict__ p, const float* __restrict__ Ws1, const float* __restrict__ bs1,
    const float* __restrict__ Ws2, const float* __restrict__ bs2, float* __restrict__ out) {
    __shared__ float W1T[64 * 32];
    __shared__ float w2[32], b1[32];
    __shared__ float stage[8][64];
    int tid = threadIdx.x;
    for (int i = tid; i < 2048; i += 256) {
        int j = i >> 6, k = i & 63;
        W1T[k * 32 + j] = Ws1[i];
    }
    if (tid < 32) { w2[tid] = Ws2[tid]; b1[tid] = bs1[tid]; }
    __syncthreads();
    const float b2 = __ldg(bs2);
    const int lane = tid & 31, w = tid >> 5;
    const int wg = blockIdx.x * 8 + w;
    const int nw = gridDim.x * 8;
    for (int nd = wg; nd < NP; nd += nw) {
        float2 v = *reinterpret_cast<const float2*>(p + (size_t)nd * HD + 2 * lane);
        stage[w][2 * lane] = v.x; stage[w][2 * lane + 1] = v.y;
        __syncwarp();
        float acc = b1[lane];
#pragma unroll 8
        for (int k = 0; k < 64; k++)
            acc = fmaf(stage[w][k], W1T[k * 32 + lane], acc);
        float s = fmaxf(acc, 0.f) * w2[lane];
#pragma unroll
        for (int off = 16; off; off >>= 1) s += __shfl_xor_sync(0xffffffffu, s, off);
        if (lane == 0) out[20 + nd] = s + b2;
        __syncwarp();
    }
}

// ---------------- orchestration ----------------
extern "C" void kernel_launch(void* const* d_in, const int* in_sizes, int n_in,
                              void* d_out, int out_size) {
    const int* x_person   = (const int*)d_in[0];
    const int* x_object   = (const int*)d_in[1];
    const int* x_location = (const int*)d_in[2];
    const int* acts_src = (const int*)d_in[3];
    const int* acts_dst = (const int*)d_in[4];
    const int* uses_src = (const int*)d_in[5];
    const int* uses_dst = (const int*)d_in[6];
    const int* at_src   = (const int*)d_in[7];
    const int* at_dst   = (const int*)d_in[8];
    const float* person_emb   = (const float*)d_in[9];
    const float* object_emb   = (const float*)d_in[10];
    const float* location_emb = (const float*)d_in[11];
    const float* Wl  = (const float*)d_in[12];
    const float* bl  = (const float*)d_in[13];
    const float* Wr  = (const float*)d_in[14];
    const float* Wc1 = (const float*)d_in[15];
    const float* bc1 = (const float*)d_in[16];
    const float* Wc2 = (const float*)d_in[17];
    const float* bc2 = (const float*)d_in[18];
    const float* Ws1 = (const float*)d_in[19];
    const float* bs1 = (const float*)d_in[20];
    const float* Ws2 = (const float*)d_in[21];
    const float* bs2 = (const float*)d_in[22];
    float* out = (float*)d_out;

    float* nodes  = nullptr; cudaGetSymbolAddress((void**)&nodes, g_nodes);
    float* means  = nullptr; cudaGetSymbolAddress((void**)&means, g_means);
    int*   csr    = nullptr; cudaGetSymbolAddress((void**)&csr, g_csr);
    int*   rowoff = nullptr; cudaGetSymbolAddress((void**)&rowoff, g_rowoff);
    int*   cnt    = nullptr; cudaGetSymbolAddress((void**)&cnt, g_cnt);
    int*   part   = nullptr; cudaGetSymbolAddress((void**)&part, g_part);
    float* sums   = nullptr; cudaGetSymbolAddress((void**)&sums, g_sums);

    int nsm = 148;
    cudaDeviceGetAttribute(&nsm, cudaDevAttrMultiProcessorCount, 0);

    const size_t NODESZ = (size_t)(NP + NO + NL) * HD;
    float* bufA = nodes;
    float* bufB = nodes + NODESZ;

    cudaFuncSetAttribute(gemm_all, cudaFuncAttributeMaxDynamicSharedMemorySize, SMEMC);

    // Phase A: embedding gathers (all node types, one launch)
    gather_all<<<((NP + NO + NL) * 16 + 255) / 256, 256>>>(
        x_person, x_object, x_location, person_emb, object_emb, location_emb, bufA);

    // Phase B: global CSR build
    zero_kernel<<<256, 256>>>((float*)cnt, (size_t)NCNT);
    count_all<<<(5 * NE + 255) / 256, 256>>>(acts_dst, uses_src, at_src, uses_dst, at_dst, cnt);
    const int NB = (NCNT + SCHUNK - 1) / SCHUNK;   // 184
    scan_reduce<<<NB, 256>>>(cnt, part, NCNT);
    scan_part<<<1, 256>>>(part, NB);
    scan_write<<<NB, 256>>>(cnt, part, rowoff, NCNT, NB);
    copy_int<<<(NCNT / 4 + 255) / 256, 256>>>(rowoff, cnt, NCNT / 4);   // cursors = rowoff
    fill_all<<<(5 * NE + 255) / 256, 256>>>(acts_src, acts_dst, uses_src, uses_dst,
                                            at_src, at_dst, cnt, csr);

    // Phase C: 3 GNN layers — high-occupancy aggregation, then dense GEMM
    float* pc = bufA;
    float* pn = bufB;
    for (int t = 0; t < 3; t++) {
        agg_all<<<8 * nsm, 256>>>(pc, means, rowoff, csr);
        gemm_all<<<nsm, NWARP * 32, SMEMC>>>(pc, pn, means, Wl, bl, Wr, t);
        float* tmp = pc; pc = pn; pn = tmp;
    }

    // Phase D: heads
    float* p = pc;
    zero_kernel<<<1, 48>>>(sums, 192);
    colsum_all<<<512, 256>>>(p, sums);
    head_kernel<<<1, 256>>>(sums, Wc1, bc1, Wc2, bc2, out);
    suspect_kernel<<<2048, 256>>>(p, Ws1, bs1, Ws2, bs2, out);
}